// round 2
// baseline (speedup 1.0000x reference)
#include <cuda_runtime.h>
#include <cstdio>

// Problem constants
#define BB    16
#define KK    2048
#define DD    512
#define INNER 1024
#define KW    5
#define MM    (BB*KK)      // 32768 rows
#define EPSV  1e-5f

// ---------------- scratch (device globals; no allocation allowed) -----------
__device__ float g_h[(size_t)MM * DD];      // rmsnorm output       64 MB
__device__ float g_a[(size_t)MM * INNER];   // a / g (in-place)    128 MB
__device__ float g_bg[(size_t)MM * INNER];  // b gate              128 MB

// ---------------- rmsnorm: one warp per row (512 floats) --------------------
__global__ __launch_bounds__(256) void rmsnorm_kernel(
    const float* __restrict__ x, const float* __restrict__ w,
    float* __restrict__ h)
{
    int row  = blockIdx.x * 8 + (threadIdx.x >> 5);
    int lane = threadIdx.x & 31;
    const float4* xp = reinterpret_cast<const float4*>(x + (size_t)row * DD);
    const float4* wp = reinterpret_cast<const float4*>(w);

    float4 v[4];
    float ss = 0.f;
#pragma unroll
    for (int j = 0; j < 4; j++) {
        v[j] = xp[lane + 32 * j];
        ss += v[j].x * v[j].x + v[j].y * v[j].y + v[j].z * v[j].z + v[j].w * v[j].w;
    }
#pragma unroll
    for (int off = 16; off > 0; off >>= 1)
        ss += __shfl_xor_sync(0xffffffffu, ss, off);

    float r = rsqrtf(ss * (1.0f / DD) + EPSV);

    float4* hp = reinterpret_cast<float4*>(h + (size_t)row * DD);
#pragma unroll
    for (int j = 0; j < 4; j++) {
        float4 wv = wp[lane + 32 * j];
        float4 o;
        o.x = v[j].x * r * wv.x;
        o.y = v[j].y * r * wv.y;
        o.z = v[j].z * r * wv.z;
        o.w = v[j].w * r * wv.w;
        hp[lane + 32 * j] = o;
    }
}

// ---------------- SIMT fp32 GEMM (NT): C[m,n] = sum_k A[m,k]*B[n,k] ---------
// A: [M,K] row-major, B: [N,K] row-major (both K-contiguous -> coalesced)
// Block tile 128x128x16, 256 threads, 8x8 per thread.
#define BMT 128
#define BNT 128
#define BKT 16
#define TMT 8
#define TNT 8

__global__ __launch_bounds__(256) void sgemm_nt(
    const float* __restrict__ A, const float* __restrict__ B,
    float* __restrict__ C, const float* __restrict__ res,
    int N, int K)
{
    __shared__ float As[BKT][BMT];
    __shared__ float Bs[BKT][BNT];

    int tid = threadIdx.x;
    int bm = blockIdx.y, bn = blockIdx.x;

    const float* Ab = A + (size_t)bm * BMT * K;
    const float* Bb = B + (size_t)bn * BNT * K;

    int lrow = tid >> 2;          // 0..63
    int lcol = (tid & 3) << 2;    // 0,4,8,12

    int ty = tid >> 4;            // 0..15 -> M direction
    int tx = tid & 15;            // 0..15 -> N direction

    float acc[TMT][TNT];
#pragma unroll
    for (int i = 0; i < TMT; i++)
#pragma unroll
        for (int j = 0; j < TNT; j++) acc[i][j] = 0.f;

    for (int k0 = 0; k0 < K; k0 += BKT) {
#pragma unroll
        for (int r = 0; r < 2; r++) {
            int row = lrow + r * 64;
            float4 va = *reinterpret_cast<const float4*>(Ab + (size_t)row * K + k0 + lcol);
            As[lcol + 0][row] = va.x;
            As[lcol + 1][row] = va.y;
            As[lcol + 2][row] = va.z;
            As[lcol + 3][row] = va.w;
            float4 vb = *reinterpret_cast<const float4*>(Bb + (size_t)row * K + k0 + lcol);
            Bs[lcol + 0][row] = vb.x;
            Bs[lcol + 1][row] = vb.y;
            Bs[lcol + 2][row] = vb.z;
            Bs[lcol + 3][row] = vb.w;
        }
        __syncthreads();

#pragma unroll
        for (int kk = 0; kk < BKT; kk++) {
            float ra[TMT], rb[TNT];
            *reinterpret_cast<float4*>(&ra[0]) = *reinterpret_cast<const float4*>(&As[kk][ty * TMT]);
            *reinterpret_cast<float4*>(&ra[4]) = *reinterpret_cast<const float4*>(&As[kk][ty * TMT + 4]);
            *reinterpret_cast<float4*>(&rb[0]) = *reinterpret_cast<const float4*>(&Bs[kk][tx * TNT]);
            *reinterpret_cast<float4*>(&rb[4]) = *reinterpret_cast<const float4*>(&Bs[kk][tx * TNT + 4]);
#pragma unroll
            for (int i = 0; i < TMT; i++)
#pragma unroll
                for (int j = 0; j < TNT; j++)
                    acc[i][j] = fmaf(ra[i], rb[j], acc[i][j]);
        }
        __syncthreads();
    }

    // epilogue (optional residual add)
    float* Cb = C + (size_t)(bm * BMT) * N + bn * BNT;
    const float* Rb = res ? res + (size_t)(bm * BMT) * N + bn * BNT : nullptr;
#pragma unroll
    for (int i = 0; i < TMT; i++) {
        int row = ty * TMT + i;
#pragma unroll
        for (int j = 0; j < TNT; j += 4) {
            float4 v = make_float4(acc[i][j], acc[i][j + 1], acc[i][j + 2], acc[i][j + 3]);
            if (Rb) {
                float4 rr = *reinterpret_cast<const float4*>(Rb + (size_t)row * N + tx * TNT + j);
                v.x += rr.x; v.y += rr.y; v.z += rr.z; v.w += rr.w;
            }
            *reinterpret_cast<float4*>(Cb + (size_t)row * N + tx * TNT + j) = v;
        }
    }
}

// ---------------- fused dwconv + bias + silu + scan + gate ------------------
// One thread per (batch, channel). Writes g IN PLACE over a (writes lag reads
// by 2 sequence positions within the thread-private column -> safe).
__global__ __launch_bounds__(256) void conv_scan_gate_kernel(
    float* __restrict__ a,               // [B,K,INNER]  in: conv input, out: g
    const float* __restrict__ bg,        // [B,K,INNER]
    const float* __restrict__ conv_w,    // [INNER,1,KW]
    const float* __restrict__ conv_b,    // [INNER]
    const float* __restrict__ alpha,
    const float* __restrict__ beta,
    const float* __restrict__ gamma,
    const float* __restrict__ delta)
{
    int idx = blockIdx.x * blockDim.x + threadIdx.x;   // 0 .. B*INNER-1
    int b = idx / INNER;
    int i = idx % INNER;

    float w0 = conv_w[i * KW + 0];
    float w1 = conv_w[i * KW + 1];
    float w2 = conv_w[i * KW + 2];
    float w3 = conv_w[i * KW + 3];
    float w4 = conv_w[i * KW + 4];
    float cb = conv_b[i];
    float asig = 1.0f / (1.0f + __expf(-alpha[i]));
    float bt = beta[i], gm = gamma[i], dl = delta[i];

    float* ap = a + (size_t)b * KK * INNER + i;
    const float* bp = bg + (size_t)b * KK * INNER + i;

    float xm2 = 0.f, xm1 = 0.f;
    float x0 = ap[0];
    float x1 = ap[(size_t)INNER];
    float s = 0.f;

    for (int k = 0; k < KK; k++) {
        float x2 = (k + 2 < KK) ? ap[(size_t)(k + 2) * INNER] : 0.f;
        float c = fmaf(w0, xm2, fmaf(w1, xm1, fmaf(w2, x0, fmaf(w3, x1, fmaf(w4, x2, cb)))));
        float u = c / (1.0f + __expf(-c));       // silu
        s = fmaf(asig, s, bt * u);               // scan recurrence
        float y = fmaf(gm, s, dl * u);
        ap[(size_t)k * INNER] = y * bp[(size_t)k * INNER];   // gate, in place
        xm2 = xm1; xm1 = x0; x0 = x1; x1 = x2;
    }
}

// ---------------- launch ----------------------------------------------------
extern "C" void kernel_launch(void* const* d_in, const int* in_sizes, int n_in,
                              void* d_out, int out_size)
{
    const float* x      = (const float*)d_in[0];
    const float* norm_w = (const float*)d_in[1];
    const float* Wa     = (const float*)d_in[2];
    const float* Wb     = (const float*)d_in[3];
    const float* conv_w = (const float*)d_in[4];
    const float* conv_b = (const float*)d_in[5];
    const float* alpha  = (const float*)d_in[6];
    const float* beta   = (const float*)d_in[7];
    const float* gamma  = (const float*)d_in[8];
    const float* delta  = (const float*)d_in[9];
    const float* Wout   = (const float*)d_in[10];
    float* out = (float*)d_out;

    float *h, *a, *bg;
    cudaGetSymbolAddress((void**)&h,  g_h);
    cudaGetSymbolAddress((void**)&a,  g_a);
    cudaGetSymbolAddress((void**)&bg, g_bg);

    // 1) rmsnorm: 32768 rows, 8 warps/block
    rmsnorm_kernel<<<MM / 8, 256>>>(x, norm_w, h);

    // 2) a = h @ Wa^T, b = h @ Wb^T   (M=32768, N=1024, K=512)
    {
        dim3 grid(INNER / BNT, MM / BMT);
        sgemm_nt<<<grid, 256>>>(h, Wa, a,  nullptr, INNER, DD);
        sgemm_nt<<<grid, 256>>>(h, Wb, bg, nullptr, INNER, DD);
    }

    // 3) fused conv+silu+scan+gate (g written in place over a)
    conv_scan_gate_kernel<<<(BB * INNER) / 256, 256>>>(
        a, bg, conv_w, conv_b, alpha, beta, gamma, delta);

    // 4) out = x + g @ Wout^T   (M=32768, N=512, K=1024)
    {
        dim3 grid(DD / BNT, MM / BMT);
        sgemm_nt<<<grid, 256>>>(a, Wout, out, x, DD, INNER);
    }
}

// round 4
// speedup vs baseline: 2.4883x; 2.4883x over previous
#include <cuda_runtime.h>
#include <cuda_bf16.h>
#include <cstdint>

// ---------------- problem constants ----------------
#define BB    16
#define KK    2048
#define DD    512
#define INNER 1024
#define KW    5
#define MM    (BB*KK)      // 32768
#define EPSV  1e-5f

// ---------------- scratch (device globals) ----------------
__device__ float          g_a [(size_t)MM * INNER];   // conv input (fp32)
__device__ float          g_bg[(size_t)MM * INNER];   // b gate     (fp32)
__device__ __nv_bfloat16  g_hh[(size_t)MM * DD];      // rmsnorm hi
__device__ __nv_bfloat16  g_hl[(size_t)MM * DD];      // rmsnorm lo
__device__ __nv_bfloat16  g_gh[(size_t)MM * INNER];   // scan out hi
__device__ __nv_bfloat16  g_gl[(size_t)MM * INNER];   // scan out lo
__device__ __nv_bfloat16  g_wah[INNER * DD], g_wal[INNER * DD];
__device__ __nv_bfloat16  g_wbh[INNER * DD], g_wbl[INNER * DD];
__device__ __nv_bfloat16  g_woh[DD * INNER], g_wol[DD * INNER];

__device__ __forceinline__ uint32_t smem_u32(const void* p) {
    uint32_t a;
    asm("{ .reg .u64 t; cvta.to.shared.u64 t, %1; cvt.u32.u64 %0, t; }"
        : "=r"(a) : "l"(p));
    return a;
}

// ---------------- rmsnorm -> bf16 hi/lo ----------------
__device__ __forceinline__ void split_store4(__nv_bfloat16* hb, __nv_bfloat16* lb,
                                             int col, float4 o) {
    __nv_bfloat16 h0 = __float2bfloat16(o.x), h1 = __float2bfloat16(o.y);
    __nv_bfloat16 h2 = __float2bfloat16(o.z), h3 = __float2bfloat16(o.w);
    __nv_bfloat16 l0 = __float2bfloat16(o.x - __bfloat162float(h0));
    __nv_bfloat16 l1 = __float2bfloat16(o.y - __bfloat162float(h1));
    __nv_bfloat16 l2 = __float2bfloat16(o.z - __bfloat162float(h2));
    __nv_bfloat16 l3 = __float2bfloat16(o.w - __bfloat162float(h3));
    __nv_bfloat162* hp = reinterpret_cast<__nv_bfloat162*>(hb + col);
    __nv_bfloat162* lp = reinterpret_cast<__nv_bfloat162*>(lb + col);
    hp[0] = __halves2bfloat162(h0, h1);
    hp[1] = __halves2bfloat162(h2, h3);
    lp[0] = __halves2bfloat162(l0, l1);
    lp[1] = __halves2bfloat162(l2, l3);
}

__global__ __launch_bounds__(256) void rmsnorm_kernel(
    const float* __restrict__ x, const float* __restrict__ w,
    __nv_bfloat16* __restrict__ hh, __nv_bfloat16* __restrict__ hl)
{
    int row  = blockIdx.x * 8 + (threadIdx.x >> 5);
    int lane = threadIdx.x & 31;
    const float4* xp = reinterpret_cast<const float4*>(x + (size_t)row * DD);
    const float4* wp = reinterpret_cast<const float4*>(w);

    float4 v[4];
    float ss = 0.f;
#pragma unroll
    for (int j = 0; j < 4; j++) {
        v[j] = xp[lane + 32 * j];
        ss += v[j].x * v[j].x + v[j].y * v[j].y + v[j].z * v[j].z + v[j].w * v[j].w;
    }
#pragma unroll
    for (int off = 16; off > 0; off >>= 1)
        ss += __shfl_xor_sync(0xffffffffu, ss, off);

    float r = rsqrtf(ss * (1.0f / DD) + EPSV);

    __nv_bfloat16* hb = hh + (size_t)row * DD;
    __nv_bfloat16* lb = hl + (size_t)row * DD;
#pragma unroll
    for (int j = 0; j < 4; j++) {
        float4 wv = wp[lane + 32 * j];
        float4 o;
        o.x = v[j].x * r * wv.x;
        o.y = v[j].y * r * wv.y;
        o.z = v[j].z * r * wv.z;
        o.w = v[j].w * r * wv.w;
        split_store4(hb, lb, (lane + 32 * j) * 4, o);
    }
}

// ---------------- fp32 -> bf16 hi/lo converter (weights) ----------------
__global__ __launch_bounds__(256) void cvt_split_kernel(
    const float* __restrict__ src, __nv_bfloat16* __restrict__ hi,
    __nv_bfloat16* __restrict__ lo, int n)
{
    int i = blockIdx.x * 256 + threadIdx.x;
    if (i < n) {
        float v = src[i];
        __nv_bfloat16 h = __float2bfloat16(v);
        hi[i] = h;
        lo[i] = __float2bfloat16(v - __bfloat162float(h));
    }
}

// ---------------- HMMA bf16x3 GEMM: C = A@B^T (+res) ----------------
// A (hi/lo): [M,K] bf16 K-major.  B (hi/lo): [N,K] bf16 K-major.
// Block 128x128, BK=32, 8 warps (2x4), warp tile 64x32.
// SMEM row stride = 40 halves (80B): 16B-aligned cp.async + conflict-free LDS.

#define RS 40                       // halves per smem row
#define TILE_H (128 * RS)           // halves per tile (5120)
#define STAGE_H (4 * TILE_H)        // halves per stage (20480)
#define GEMM_SMEM_BYTES (2 * STAGE_H * 2)   // 81920

#define MMA_BF16(c, a, b)                                               \
    asm volatile(                                                       \
        "mma.sync.aligned.m16n8k16.row.col.f32.bf16.bf16.f32 "          \
        "{%0,%1,%2,%3}, {%4,%5,%6,%7}, {%8,%9}, {%0,%1,%2,%3};"         \
        : "+f"((c)[0]), "+f"((c)[1]), "+f"((c)[2]), "+f"((c)[3])        \
        : "r"((a)[0]), "r"((a)[1]), "r"((a)[2]), "r"((a)[3]),           \
          "r"((b)[0]), "r"((b)[1]))

__global__ __launch_bounds__(256) void gemm_bf16x3(
    const __nv_bfloat16* __restrict__ Ah, const __nv_bfloat16* __restrict__ Al,
    const __nv_bfloat16* __restrict__ Bh, const __nv_bfloat16* __restrict__ Bl,
    float* __restrict__ C, const float* __restrict__ res, int N, int K)
{
    extern __shared__ uint16_t sm[];

    const int tid  = threadIdx.x;
    const int lane = tid & 31;
    const int wid  = tid >> 5;
    const int wm   = wid >> 2;        // 0..1 -> m offset wm*64
    const int wn   = wid & 3;         // 0..3 -> n offset wn*32
    const int r    = lane >> 2;       // 0..7
    const int cp   = (lane & 3) * 2;  // 0,2,4,6

    const size_t mBase = (size_t)blockIdx.y * 128;
    const size_t nBase = (size_t)blockIdx.x * 128;

    const __nv_bfloat16* srcs[4] = {
        Ah + mBase * K, Al + mBase * K, Bh + nBase * K, Bl + nBase * K };

    const uint32_t smem_base = smem_u32(sm);

    // ---- async stage loader: 4 tiles of 128 rows x 32 halves ----
    auto load_stage = [&](int s, int kt) {
        uint32_t sb = smem_base + (uint32_t)s * (STAGE_H * 2);
#pragma unroll
        for (int t = 0; t < 4; t++) {
            const __nv_bfloat16* src = srcs[t];
#pragma unroll
            for (int rep = 0; rep < 2; rep++) {
                int o   = tid + rep * 256;      // 0..511
                int row = o >> 2;
                int seg = o & 3;
                uint32_t dst = sb + (uint32_t)t * (TILE_H * 2) + row * (RS * 2) + seg * 16;
                const void* g = src + (size_t)row * K + kt * 32 + seg * 8;
                asm volatile("cp.async.cg.shared.global [%0], [%1], 16;"
                             :: "r"(dst), "l"(g));
            }
        }
        asm volatile("cp.async.commit_group;" ::: "memory");
    };

    float acc[4][4][4];
#pragma unroll
    for (int i = 0; i < 4; i++)
#pragma unroll
        for (int j = 0; j < 4; j++)
#pragma unroll
            for (int q = 0; q < 4; q++) acc[i][j][q] = 0.f;

    const int nkt = K >> 5;

    load_stage(0, 0);

    for (int kt = 0; kt < nkt; kt++) {
        if (kt + 1 < nkt) {
            load_stage((kt + 1) & 1, kt + 1);
            asm volatile("cp.async.wait_group 1;" ::: "memory");
        } else {
            asm volatile("cp.async.wait_group 0;" ::: "memory");
        }
        __syncthreads();

        const uint16_t* sAh = sm + (kt & 1) * STAGE_H;
        const uint16_t* sAl = sAh + TILE_H;
        const uint16_t* sBh = sAh + 2 * TILE_H;
        const uint16_t* sBl = sAh + 3 * TILE_H;

#pragma unroll
        for (int k16 = 0; k16 < 32; k16 += 16) {
            uint32_t bh[4][2], bl[4][2];
#pragma unroll
            for (int ni = 0; ni < 4; ni++) {
                const uint16_t* pb = sBh + (wn * 32 + ni * 8 + r) * RS + k16 + cp;
                bh[ni][0] = *reinterpret_cast<const uint32_t*>(pb);
                bh[ni][1] = *reinterpret_cast<const uint32_t*>(pb + 8);
                const uint16_t* pl = pb + 3 * TILE_H - 2 * TILE_H; // sBl offset from sBh
                pl = pb + TILE_H;
                bl[ni][0] = *reinterpret_cast<const uint32_t*>(pl);
                bl[ni][1] = *reinterpret_cast<const uint32_t*>(pl + 8);
            }
#pragma unroll
            for (int mi = 0; mi < 4; mi++) {
                const uint16_t* pa = sAh + (wm * 64 + mi * 16 + r) * RS + k16 + cp;
                uint32_t ah[4], al[4];
                ah[0] = *reinterpret_cast<const uint32_t*>(pa);
                ah[1] = *reinterpret_cast<const uint32_t*>(pa + 8 * RS);
                ah[2] = *reinterpret_cast<const uint32_t*>(pa + 8);
                ah[3] = *reinterpret_cast<const uint32_t*>(pa + 8 * RS + 8);
                const uint16_t* pal = pa + TILE_H;
                al[0] = *reinterpret_cast<const uint32_t*>(pal);
                al[1] = *reinterpret_cast<const uint32_t*>(pal + 8 * RS);
                al[2] = *reinterpret_cast<const uint32_t*>(pal + 8);
                al[3] = *reinterpret_cast<const uint32_t*>(pal + 8 * RS + 8);
#pragma unroll
                for (int ni = 0; ni < 4; ni++) {
                    MMA_BF16(acc[mi][ni], ah, bh[ni]);
                    MMA_BF16(acc[mi][ni], ah, bl[ni]);
                    MMA_BF16(acc[mi][ni], al, bh[ni]);
                }
            }
        }
        __syncthreads();
    }

    // ---- epilogue ----
#pragma unroll
    for (int mi = 0; mi < 4; mi++) {
        size_t row0 = mBase + wm * 64 + mi * 16 + r;
#pragma unroll
        for (int ni = 0; ni < 4; ni++) {
            size_t col = nBase + wn * 32 + ni * 8 + cp;
            float2 v0 = make_float2(acc[mi][ni][0], acc[mi][ni][1]);
            float2 v1 = make_float2(acc[mi][ni][2], acc[mi][ni][3]);
            if (res) {
                float2 r0 = *reinterpret_cast<const float2*>(res + row0 * N + col);
                float2 r1 = *reinterpret_cast<const float2*>(res + (row0 + 8) * N + col);
                v0.x += r0.x; v0.y += r0.y;
                v1.x += r1.x; v1.y += r1.y;
            }
            *reinterpret_cast<float2*>(C + row0 * N + col) = v0;
            *reinterpret_cast<float2*>(C + (row0 + 8) * N + col) = v1;
        }
    }
}

// ---------------- fused dwconv + bias + silu + scan + gate -> bf16 hi/lo ----
__global__ __launch_bounds__(256) void conv_scan_gate_kernel(
    const float* __restrict__ a, const float* __restrict__ bg,
    __nv_bfloat16* __restrict__ gh, __nv_bfloat16* __restrict__ gl,
    const float* __restrict__ conv_w, const float* __restrict__ conv_b,
    const float* __restrict__ alpha, const float* __restrict__ beta,
    const float* __restrict__ gamma, const float* __restrict__ delta)
{
    int idx = blockIdx.x * 256 + threadIdx.x;   // 0 .. B*INNER-1
    int b = idx >> 10;
    int i = idx & (INNER - 1);

    float w0 = conv_w[i * KW + 0];
    float w1 = conv_w[i * KW + 1];
    float w2 = conv_w[i * KW + 2];
    float w3 = conv_w[i * KW + 3];
    float w4 = conv_w[i * KW + 4];
    float cb = conv_b[i];
    float asig = 1.0f / (1.0f + __expf(-alpha[i]));
    float bt = beta[i], gm = gamma[i], dl = delta[i];

    const float* ap = a  + (size_t)b * KK * INNER + i;
    const float* bp = bg + (size_t)b * KK * INNER + i;
    __nv_bfloat16* ghp = gh + (size_t)b * KK * INNER + i;
    __nv_bfloat16* glp = gl + (size_t)b * KK * INNER + i;

    float xm2 = 0.f, xm1 = 0.f;
    float x0 = ap[0];
    float x1 = ap[(size_t)INNER];
    float s = 0.f;

    for (int k = 0; k < KK; k += 4) {
        float xn[4], bb[4];
#pragma unroll
        for (int j = 0; j < 4; j++) {
            int kk = k + 2 + j;
            xn[j] = (kk < KK) ? ap[(size_t)kk * INNER] : 0.f;
        }
#pragma unroll
        for (int j = 0; j < 4; j++)
            bb[j] = bp[(size_t)(k + j) * INNER];
#pragma unroll
        for (int j = 0; j < 4; j++) {
            float x2 = xn[j];
            float c = fmaf(w0, xm2, fmaf(w1, xm1, fmaf(w2, x0, fmaf(w3, x1, fmaf(w4, x2, cb)))));
            float u = c / (1.0f + __expf(-c));
            s = fmaf(asig, s, bt * u);
            float y = fmaf(gm, s, dl * u);
            float g = y * bb[j];
            __nv_bfloat16 hi = __float2bfloat16(g);
            ghp[(size_t)(k + j) * INNER] = hi;
            glp[(size_t)(k + j) * INNER] = __float2bfloat16(g - __bfloat162float(hi));
            xm2 = xm1; xm1 = x0; x0 = x1; x1 = x2;
        }
    }
}

// ---------------- launch ----------------
extern "C" void kernel_launch(void* const* d_in, const int* in_sizes, int n_in,
                              void* d_out, int out_size)
{
    const float* x      = (const float*)d_in[0];
    const float* norm_w = (const float*)d_in[1];
    const float* Wa     = (const float*)d_in[2];
    const float* Wb     = (const float*)d_in[3];
    const float* conv_w = (const float*)d_in[4];
    const float* conv_b = (const float*)d_in[5];
    const float* alpha  = (const float*)d_in[6];
    const float* beta   = (const float*)d_in[7];
    const float* gamma  = (const float*)d_in[8];
    const float* delta  = (const float*)d_in[9];
    const float* Wout   = (const float*)d_in[10];
    float* out = (float*)d_out;

    float *a, *bg;
    __nv_bfloat16 *hh, *hl, *gh, *gl, *wah, *wal, *wbh, *wbl, *woh, *wol;
    cudaGetSymbolAddress((void**)&a,   g_a);
    cudaGetSymbolAddress((void**)&bg,  g_bg);
    cudaGetSymbolAddress((void**)&hh,  g_hh);
    cudaGetSymbolAddress((void**)&hl,  g_hl);
    cudaGetSymbolAddress((void**)&gh,  g_gh);
    cudaGetSymbolAddress((void**)&gl,  g_gl);
    cudaGetSymbolAddress((void**)&wah, g_wah);
    cudaGetSymbolAddress((void**)&wal, g_wal);
    cudaGetSymbolAddress((void**)&wbh, g_wbh);
    cudaGetSymbolAddress((void**)&wbl, g_wbl);
    cudaGetSymbolAddress((void**)&woh, g_woh);
    cudaGetSymbolAddress((void**)&wol, g_wol);

    cudaFuncSetAttribute(gemm_bf16x3,
                         cudaFuncAttributeMaxDynamicSharedMemorySize, GEMM_SMEM_BYTES);

    // 1) rmsnorm -> bf16 hi/lo
    rmsnorm_kernel<<<MM / 8, 256>>>(x, norm_w, hh, hl);

    // 2) weight conversions
    cvt_split_kernel<<<(INNER * DD + 255) / 256, 256>>>(Wa,   wah, wal, INNER * DD);
    cvt_split_kernel<<<(INNER * DD + 255) / 256, 256>>>(Wb,   wbh, wbl, INNER * DD);
    cvt_split_kernel<<<(DD * INNER + 255) / 256, 256>>>(Wout, woh, wol, DD * INNER);

    // 3) a = h @ Wa^T, b = h @ Wb^T   (M=32768, N=1024, K=512)
    {
        dim3 grid(INNER / 128, MM / 128);
        gemm_bf16x3<<<grid, 256, GEMM_SMEM_BYTES>>>(hh, hl, wah, wal, a,  nullptr, INNER, DD);
        gemm_bf16x3<<<grid, 256, GEMM_SMEM_BYTES>>>(hh, hl, wbh, wbl, bg, nullptr, INNER, DD);
    }

    // 4) fused conv+silu+scan+gate -> g (bf16 hi/lo)
    conv_scan_gate_kernel<<<(BB * INNER) / 256, 256>>>(
        a, bg, gh, gl, conv_w, conv_b, alpha, beta, gamma, delta);

    // 5) out = x + g @ Wout^T   (M=32768, N=512, K=1024)
    {
        dim3 grid(DD / 128, MM / 128);
        gemm_bf16x3<<<grid, 256, GEMM_SMEM_BYTES>>>(gh, gl, woh, wol, out, x, DD, INNER);
    }
}

// round 5
// speedup vs baseline: 3.7581x; 1.5103x over previous
#include <cuda_runtime.h>
#include <cuda_bf16.h>
#include <cstdint>

// ---------------- problem constants ----------------
#define BB    16
#define KK    2048
#define DD    512
#define INNER 1024
#define KW    5
#define MM    (BB*KK)      // 32768
#define EPSV  1e-5f
#define NC    8            // scan chunks
#define CL    (KK/NC)      // 256

// ---------------- scratch (device globals) ----------------
__device__ float          g_a [(size_t)MM * INNER];   // conv input (fp32)
__device__ float          g_bg[(size_t)MM * INNER];   // b gate     (fp32)
__device__ __nv_bfloat16  g_hh[(size_t)MM * DD];      // rmsnorm hi
__device__ __nv_bfloat16  g_hl[(size_t)MM * DD];      // rmsnorm lo
__device__ __nv_bfloat16  g_gh[(size_t)MM * INNER];   // scan out hi
__device__ __nv_bfloat16  g_gl[(size_t)MM * INNER];   // scan out lo
__device__ __nv_bfloat16  g_wah[INNER * DD], g_wal[INNER * DD];
__device__ __nv_bfloat16  g_wbh[INNER * DD], g_wbl[INNER * DD];
__device__ __nv_bfloat16  g_woh[DD * INNER], g_wol[DD * INNER];
__device__ float          g_state[BB * NC * INNER];   // chunk-local final states
__device__ float          g_sin  [BB * NC * INNER];   // carried-in states

__device__ __forceinline__ uint32_t smem_u32(const void* p) {
    uint32_t a;
    asm("{ .reg .u64 t; cvta.to.shared.u64 t, %1; cvt.u32.u64 %0, t; }"
        : "=r"(a) : "l"(p));
    return a;
}

// ---------------- rmsnorm -> bf16 hi/lo ----------------
__device__ __forceinline__ void split_store4(__nv_bfloat16* hb, __nv_bfloat16* lb,
                                             int col, float4 o) {
    __nv_bfloat16 h0 = __float2bfloat16(o.x), h1 = __float2bfloat16(o.y);
    __nv_bfloat16 h2 = __float2bfloat16(o.z), h3 = __float2bfloat16(o.w);
    __nv_bfloat16 l0 = __float2bfloat16(o.x - __bfloat162float(h0));
    __nv_bfloat16 l1 = __float2bfloat16(o.y - __bfloat162float(h1));
    __nv_bfloat16 l2 = __float2bfloat16(o.z - __bfloat162float(h2));
    __nv_bfloat16 l3 = __float2bfloat16(o.w - __bfloat162float(h3));
    __nv_bfloat162* hp = reinterpret_cast<__nv_bfloat162*>(hb + col);
    __nv_bfloat162* lp = reinterpret_cast<__nv_bfloat162*>(lb + col);
    hp[0] = __halves2bfloat162(h0, h1);
    hp[1] = __halves2bfloat162(h2, h3);
    lp[0] = __halves2bfloat162(l0, l1);
    lp[1] = __halves2bfloat162(l2, l3);
}

__global__ __launch_bounds__(256) void rmsnorm_kernel(
    const float* __restrict__ x, const float* __restrict__ w,
    __nv_bfloat16* __restrict__ hh, __nv_bfloat16* __restrict__ hl)
{
    int row  = blockIdx.x * 8 + (threadIdx.x >> 5);
    int lane = threadIdx.x & 31;
    const float4* xp = reinterpret_cast<const float4*>(x + (size_t)row * DD);
    const float4* wp = reinterpret_cast<const float4*>(w);

    float4 v[4];
    float ss = 0.f;
#pragma unroll
    for (int j = 0; j < 4; j++) {
        v[j] = xp[lane + 32 * j];
        ss += v[j].x * v[j].x + v[j].y * v[j].y + v[j].z * v[j].z + v[j].w * v[j].w;
    }
#pragma unroll
    for (int off = 16; off > 0; off >>= 1)
        ss += __shfl_xor_sync(0xffffffffu, ss, off);

    float r = rsqrtf(ss * (1.0f / DD) + EPSV);

    __nv_bfloat16* hb = hh + (size_t)row * DD;
    __nv_bfloat16* lb = hl + (size_t)row * DD;
#pragma unroll
    for (int j = 0; j < 4; j++) {
        float4 wv = wp[lane + 32 * j];
        float4 o;
        o.x = v[j].x * r * wv.x;
        o.y = v[j].y * r * wv.y;
        o.z = v[j].z * r * wv.z;
        o.w = v[j].w * r * wv.w;
        split_store4(hb, lb, (lane + 32 * j) * 4, o);
    }
}

// ---------------- fp32 -> bf16 hi/lo converter (weights) ----------------
__global__ __launch_bounds__(256) void cvt_split_kernel(
    const float* __restrict__ src, __nv_bfloat16* __restrict__ hi,
    __nv_bfloat16* __restrict__ lo, int n)
{
    int i = blockIdx.x * 256 + threadIdx.x;
    if (i < n) {
        float v = src[i];
        __nv_bfloat16 h = __float2bfloat16(v);
        hi[i] = h;
        lo[i] = __float2bfloat16(v - __bfloat162float(h));
    }
}

// ---------------- HMMA bf16x3 GEMM with ldmatrix ----------------
// A (hi/lo): [M,K] bf16 K-major.  B (hi/lo): [N,K] bf16 K-major.
// Block 128x128, BK=32, 8 warps (2x4), warp tile 64x32.
// SMEM row stride = 40 halves (80B): 16B-aligned cp.async + conflict-free LDSM.

#define RS 40                       // halves per smem row
#define TILE_H (128 * RS)           // halves per tile (5120)
#define TB (TILE_H * 2)             // bytes per tile (10240)
#define STAGE_H (4 * TILE_H)        // halves per stage
#define GEMM_SMEM_BYTES (2 * STAGE_H * 2)   // 81920

#define MMA_BF16(c, a, b)                                               \
    asm volatile(                                                       \
        "mma.sync.aligned.m16n8k16.row.col.f32.bf16.bf16.f32 "          \
        "{%0,%1,%2,%3}, {%4,%5,%6,%7}, {%8,%9}, {%0,%1,%2,%3};"         \
        : "+f"((c)[0]), "+f"((c)[1]), "+f"((c)[2]), "+f"((c)[3])        \
        : "r"((a)[0]), "r"((a)[1]), "r"((a)[2]), "r"((a)[3]),           \
          "r"((b)[0]), "r"((b)[1]))

#define LDSM4(r0, r1, r2, r3, addr)                                     \
    asm volatile("ldmatrix.sync.aligned.m8n8.x4.shared.b16 "            \
                 "{%0,%1,%2,%3}, [%4];"                                 \
                 : "=r"(r0), "=r"(r1), "=r"(r2), "=r"(r3) : "r"(addr))

__global__ __launch_bounds__(256, 2) void gemm_bf16x3(
    const __nv_bfloat16* __restrict__ Ah, const __nv_bfloat16* __restrict__ Al,
    const __nv_bfloat16* __restrict__ Bh, const __nv_bfloat16* __restrict__ Bl,
    float* __restrict__ C, const float* __restrict__ res, int N, int K)
{
    extern __shared__ uint16_t sm[];

    const int tid  = threadIdx.x;
    const int lane = tid & 31;
    const int wid  = tid >> 5;
    const int wm   = wid >> 2;        // 0..1 -> m offset wm*64
    const int wn   = wid & 3;         // 0..3 -> n offset wn*32
    const int r    = lane >> 2;       // 0..7
    const int cp   = (lane & 3) * 2;  // 0,2,4,6

    const size_t mBase = (size_t)blockIdx.y * 128;
    const size_t nBase = (size_t)blockIdx.x * 128;

    const __nv_bfloat16* srcs[4] = {
        Ah + mBase * K, Al + mBase * K, Bh + nBase * K, Bl + nBase * K };

    const uint32_t smem_base = smem_u32(sm);

    // ldmatrix per-lane byte offsets (within a tile)
    // A x4: m0 rows0-7/k0-7, m1 rows8-15/k0-7, m2 rows0-7/k8-15, m3 rows8-15/k8-15
    const uint32_t aLaneOff =
        (uint32_t)(((wm * 64 + ((lane >> 3) & 1) * 8 + (lane & 7)) * RS
                    + (lane >> 4) * 8) * 2);
    // B x4: m0 n0-7/k0-7, m1 n0-7/k8-15, m2 n8-15/k0-7, m3 n8-15/k8-15
    const uint32_t bLaneOff =
        (uint32_t)(((wn * 32 + ((lane >> 4) & 1) * 8 + (lane & 7)) * RS
                    + ((lane >> 3) & 1) * 8) * 2);

    // ---- async stage loader: 4 tiles of 128 rows x 32 halves ----
    auto load_stage = [&](int s, int kt) {
        uint32_t sb = smem_base + (uint32_t)s * (STAGE_H * 2);
#pragma unroll
        for (int t = 0; t < 4; t++) {
            const __nv_bfloat16* src = srcs[t];
#pragma unroll
            for (int rep = 0; rep < 2; rep++) {
                int o   = tid + rep * 256;      // 0..511
                int row = o >> 2;
                int seg = o & 3;
                uint32_t dst = sb + (uint32_t)t * TB + row * (RS * 2) + seg * 16;
                const void* g = src + (size_t)row * K + kt * 32 + seg * 8;
                asm volatile("cp.async.cg.shared.global [%0], [%1], 16;"
                             :: "r"(dst), "l"(g));
            }
        }
        asm volatile("cp.async.commit_group;" ::: "memory");
    };

    float acc[4][4][4];
#pragma unroll
    for (int i = 0; i < 4; i++)
#pragma unroll
        for (int j = 0; j < 4; j++)
#pragma unroll
            for (int q = 0; q < 4; q++) acc[i][j][q] = 0.f;

    const int nkt = K >> 5;

    load_stage(0, 0);

    for (int kt = 0; kt < nkt; kt++) {
        if (kt + 1 < nkt) {
            load_stage((kt + 1) & 1, kt + 1);
            asm volatile("cp.async.wait_group 1;" ::: "memory");
        } else {
            asm volatile("cp.async.wait_group 0;" ::: "memory");
        }
        __syncthreads();

        uint32_t sb = smem_base + (uint32_t)(kt & 1) * (STAGE_H * 2);

#pragma unroll
        for (int k16 = 0; k16 < 32; k16 += 16) {
            uint32_t bh[4][2], bl[4][2];
#pragma unroll
            for (int j = 0; j < 2; j++) {
                uint32_t ad = sb + 2 * TB + bLaneOff
                            + (uint32_t)((j * 16 * RS + k16) * 2);
                LDSM4(bh[2*j][0], bh[2*j][1], bh[2*j+1][0], bh[2*j+1][1], ad);
                LDSM4(bl[2*j][0], bl[2*j][1], bl[2*j+1][0], bl[2*j+1][1], ad + TB);
            }
#pragma unroll
            for (int mi = 0; mi < 4; mi++) {
                uint32_t ah[4], al[4];
                uint32_t ad = sb + aLaneOff + (uint32_t)((mi * 16 * RS + k16) * 2);
                LDSM4(ah[0], ah[1], ah[2], ah[3], ad);
                LDSM4(al[0], al[1], al[2], al[3], ad + TB);
#pragma unroll
                for (int ni = 0; ni < 4; ni++) {
                    MMA_BF16(acc[mi][ni], ah, bh[ni]);
                    MMA_BF16(acc[mi][ni], ah, bl[ni]);
                    MMA_BF16(acc[mi][ni], al, bh[ni]);
                }
            }
        }
        __syncthreads();
    }

    // ---- epilogue ----
#pragma unroll
    for (int mi = 0; mi < 4; mi++) {
        size_t row0 = mBase + wm * 64 + mi * 16 + r;
#pragma unroll
        for (int ni = 0; ni < 4; ni++) {
            size_t col = nBase + wn * 32 + ni * 8 + cp;
            float2 v0 = make_float2(acc[mi][ni][0], acc[mi][ni][1]);
            float2 v1 = make_float2(acc[mi][ni][2], acc[mi][ni][3]);
            if (res) {
                float2 r0 = *reinterpret_cast<const float2*>(res + row0 * N + col);
                float2 r1 = *reinterpret_cast<const float2*>(res + (row0 + 8) * N + col);
                v0.x += r0.x; v0.y += r0.y;
                v1.x += r1.x; v1.y += r1.y;
            }
            *reinterpret_cast<float2*>(C + row0 * N + col) = v0;
            *reinterpret_cast<float2*>(C + (row0 + 8) * N + col) = v1;
        }
    }
}

// ---------------- chunked parallel scan: pass 1 (chunk-local states) --------
__global__ __launch_bounds__(256) void scan_state_kernel(
    const float* __restrict__ a,
    const float* __restrict__ conv_w, const float* __restrict__ conv_b,
    const float* __restrict__ alpha, const float* __restrict__ beta,
    float* __restrict__ S)
{
    int idx = blockIdx.x * 256 + threadIdx.x;   // 0 .. B*NC*INNER-1
    int i = idx & (INNER - 1);
    int c = (idx >> 10) & (NC - 1);
    int b = idx >> 13;

    float w0 = conv_w[i * KW + 0];
    float w1 = conv_w[i * KW + 1];
    float w2 = conv_w[i * KW + 2];
    float w3 = conv_w[i * KW + 3];
    float w4 = conv_w[i * KW + 4];
    float cb = conv_b[i];
    float asig = 1.0f / (1.0f + __expf(-alpha[i]));
    float bt = beta[i];

    const float* col = a + (size_t)b * KK * INNER + i;
    int k0 = c * CL;

    float xm2 = (c > 0) ? col[(size_t)(k0 - 2) * INNER] : 0.f;
    float xm1 = (c > 0) ? col[(size_t)(k0 - 1) * INNER] : 0.f;
    float x0 = col[(size_t)k0 * INNER];
    float x1 = col[(size_t)(k0 + 1) * INNER];
    float s = 0.f;

    for (int k = 0; k < CL; k += 4) {
        float xn[4];
#pragma unroll
        for (int j = 0; j < 4; j++) {
            int kk = k0 + k + 2 + j;
            xn[j] = (kk < KK) ? col[(size_t)kk * INNER] : 0.f;
        }
#pragma unroll
        for (int j = 0; j < 4; j++) {
            float x2 = xn[j];
            float cc = fmaf(w0, xm2, fmaf(w1, xm1, fmaf(w2, x0, fmaf(w3, x1, fmaf(w4, x2, cb)))));
            float u = cc / (1.0f + __expf(-cc));
            s = fmaf(asig, s, bt * u);
            xm2 = xm1; xm1 = x0; x0 = x1; x1 = x2;
        }
    }
    S[((size_t)b * NC + c) * INNER + i] = s;
}

// ---------------- scan pass 2: prefix of chunk states ----------------
__global__ __launch_bounds__(256) void scan_prefix_kernel(
    const float* __restrict__ S, const float* __restrict__ alpha,
    float* __restrict__ Sin)
{
    int idx = blockIdx.x * 256 + threadIdx.x;   // 0 .. B*INNER-1
    int i = idx & (INNER - 1);
    int b = idx >> 10;

    float a = 1.0f / (1.0f + __expf(-alpha[i]));
    float aL = a;
#pragma unroll
    for (int q = 0; q < 8; q++) aL *= aL;       // a^256

    float s = 0.f;
#pragma unroll
    for (int c = 0; c < NC; c++) {
        size_t o = ((size_t)b * NC + c) * INNER + i;
        Sin[o] = s;
        s = fmaf(aL, s, S[o]);
    }
}

// ---------------- scan pass 3: apply (conv+silu+scan+gate -> bf16 hi/lo) ----
__global__ __launch_bounds__(256) void scan_apply_kernel(
    const float* __restrict__ a, const float* __restrict__ bg,
    const float* __restrict__ Sin,
    __nv_bfloat16* __restrict__ gh, __nv_bfloat16* __restrict__ gl,
    const float* __restrict__ conv_w, const float* __restrict__ conv_b,
    const float* __restrict__ alpha, const float* __restrict__ beta,
    const float* __restrict__ gamma, const float* __restrict__ delta)
{
    int idx = blockIdx.x * 256 + threadIdx.x;   // 0 .. B*NC*INNER-1
    int i = idx & (INNER - 1);
    int c = (idx >> 10) & (NC - 1);
    int b = idx >> 13;

    float w0 = conv_w[i * KW + 0];
    float w1 = conv_w[i * KW + 1];
    float w2 = conv_w[i * KW + 2];
    float w3 = conv_w[i * KW + 3];
    float w4 = conv_w[i * KW + 4];
    float cb = conv_b[i];
    float asig = 1.0f / (1.0f + __expf(-alpha[i]));
    float bt = beta[i], gm = gamma[i], dl = delta[i];

    const float* col = a  + (size_t)b * KK * INNER + i;
    const float* bp  = bg + (size_t)b * KK * INNER + i;
    __nv_bfloat16* ghp = gh + (size_t)b * KK * INNER + i;
    __nv_bfloat16* glp = gl + (size_t)b * KK * INNER + i;
    int k0 = c * CL;

    float xm2 = (c > 0) ? col[(size_t)(k0 - 2) * INNER] : 0.f;
    float xm1 = (c > 0) ? col[(size_t)(k0 - 1) * INNER] : 0.f;
    float x0 = col[(size_t)k0 * INNER];
    float x1 = col[(size_t)(k0 + 1) * INNER];
    float s = Sin[((size_t)b * NC + c) * INNER + i];

    for (int k = 0; k < CL; k += 4) {
        float xn[4], bb[4];
#pragma unroll
        for (int j = 0; j < 4; j++) {
            int kk = k0 + k + 2 + j;
            xn[j] = (kk < KK) ? col[(size_t)kk * INNER] : 0.f;
        }
#pragma unroll
        for (int j = 0; j < 4; j++)
            bb[j] = bp[(size_t)(k0 + k + j) * INNER];
#pragma unroll
        for (int j = 0; j < 4; j++) {
            float x2 = xn[j];
            float cc = fmaf(w0, xm2, fmaf(w1, xm1, fmaf(w2, x0, fmaf(w3, x1, fmaf(w4, x2, cb)))));
            float u = cc / (1.0f + __expf(-cc));
            s = fmaf(asig, s, bt * u);
            float y = fmaf(gm, s, dl * u);
            float g = y * bb[j];
            __nv_bfloat16 hi = __float2bfloat16(g);
            ghp[(size_t)(k0 + k + j) * INNER] = hi;
            glp[(size_t)(k0 + k + j) * INNER] = __float2bfloat16(g - __bfloat162float(hi));
            xm2 = xm1; xm1 = x0; x0 = x1; x1 = x2;
        }
    }
}

// ---------------- launch ----------------
extern "C" void kernel_launch(void* const* d_in, const int* in_sizes, int n_in,
                              void* d_out, int out_size)
{
    const float* x      = (const float*)d_in[0];
    const float* norm_w = (const float*)d_in[1];
    const float* Wa     = (const float*)d_in[2];
    const float* Wb     = (const float*)d_in[3];
    const float* conv_w = (const float*)d_in[4];
    const float* conv_b = (const float*)d_in[5];
    const float* alpha  = (const float*)d_in[6];
    const float* beta   = (const float*)d_in[7];
    const float* gamma  = (const float*)d_in[8];
    const float* delta  = (const float*)d_in[9];
    const float* Wout   = (const float*)d_in[10];
    float* out = (float*)d_out;

    float *a, *bg, *st, *sin;
    __nv_bfloat16 *hh, *hl, *gh, *gl, *wah, *wal, *wbh, *wbl, *woh, *wol;
    cudaGetSymbolAddress((void**)&a,   g_a);
    cudaGetSymbolAddress((void**)&bg,  g_bg);
    cudaGetSymbolAddress((void**)&st,  g_state);
    cudaGetSymbolAddress((void**)&sin, g_sin);
    cudaGetSymbolAddress((void**)&hh,  g_hh);
    cudaGetSymbolAddress((void**)&hl,  g_hl);
    cudaGetSymbolAddress((void**)&gh,  g_gh);
    cudaGetSymbolAddress((void**)&gl,  g_gl);
    cudaGetSymbolAddress((void**)&wah, g_wah);
    cudaGetSymbolAddress((void**)&wal, g_wal);
    cudaGetSymbolAddress((void**)&wbh, g_wbh);
    cudaGetSymbolAddress((void**)&wbl, g_wbl);
    cudaGetSymbolAddress((void**)&woh, g_woh);
    cudaGetSymbolAddress((void**)&wol, g_wol);

    cudaFuncSetAttribute(gemm_bf16x3,
                         cudaFuncAttributeMaxDynamicSharedMemorySize, GEMM_SMEM_BYTES);

    // 1) rmsnorm -> bf16 hi/lo
    rmsnorm_kernel<<<MM / 8, 256>>>(x, norm_w, hh, hl);

    // 2) weight conversions
    cvt_split_kernel<<<(INNER * DD + 255) / 256, 256>>>(Wa,   wah, wal, INNER * DD);
    cvt_split_kernel<<<(INNER * DD + 255) / 256, 256>>>(Wb,   wbh, wbl, INNER * DD);
    cvt_split_kernel<<<(DD * INNER + 255) / 256, 256>>>(Wout, woh, wol, DD * INNER);

    // 3) a = h @ Wa^T, b = h @ Wb^T   (M=32768, N=1024, K=512)
    {
        dim3 grid(INNER / 128, MM / 128);
        gemm_bf16x3<<<grid, 256, GEMM_SMEM_BYTES>>>(hh, hl, wah, wal, a,  nullptr, INNER, DD);
        gemm_bf16x3<<<grid, 256, GEMM_SMEM_BYTES>>>(hh, hl, wbh, wbl, bg, nullptr, INNER, DD);
    }

    // 4) chunked parallel scan (3 passes)
    scan_state_kernel<<<BB * NC * INNER / 256, 256>>>(a, conv_w, conv_b, alpha, beta, st);
    scan_prefix_kernel<<<BB * INNER / 256, 256>>>(st, alpha, sin);
    scan_apply_kernel<<<BB * NC * INNER / 256, 256>>>(
        a, bg, sin, gh, gl, conv_w, conv_b, alpha, beta, gamma, delta);

    // 5) out = x + g @ Wout^T   (M=32768, N=512, K=1024)
    {
        dim3 grid(DD / 128, MM / 128);
        gemm_bf16x3<<<grid, 256, GEMM_SMEM_BYTES>>>(gh, gl, woh, wol, out, x, DD, INNER);
    }
}

// round 6
// speedup vs baseline: 5.0537x; 1.3448x over previous
#include <cuda_runtime.h>
#include <cuda_fp16.h>
#include <cstdint>

// ---------------- problem constants ----------------
#define BB    16
#define KK    2048
#define DD    512
#define INNER 1024
#define KW    5
#define MM    (BB*KK)      // 32768
#define EPSV  1e-5f
#define NC    8            // scan chunks
#define CL    (KK/NC)      // 256

// ---------------- scratch (device globals) ----------------
__device__ float   g_a [(size_t)MM * INNER];   // conv input (fp32)
__device__ float   g_bg[(size_t)MM * INNER];   // b gate     (fp32)
__device__ __half  g_h16[(size_t)MM * DD];     // rmsnorm out (fp16)
__device__ __half  g_g16[(size_t)MM * INNER];  // scan out    (fp16)
__device__ __half  g_wah[INNER * DD], g_wal[INNER * DD];
__device__ __half  g_wbh[INNER * DD], g_wbl[INNER * DD];
__device__ __half  g_woh[DD * INNER], g_wol[DD * INNER];
__device__ float   g_state[BB * NC * INNER];   // chunk-local final states
__device__ float   g_sin  [BB * NC * INNER];   // carried-in states

__device__ __forceinline__ uint32_t smem_u32(const void* p) {
    uint32_t a;
    asm("{ .reg .u64 t; cvta.to.shared.u64 t, %1; cvt.u32.u64 %0, t; }"
        : "=r"(a) : "l"(p));
    return a;
}

// ---------------- rmsnorm -> fp16 ----------------
__global__ __launch_bounds__(256) void rmsnorm_kernel(
    const float* __restrict__ x, const float* __restrict__ w,
    __half* __restrict__ h16)
{
    int row  = blockIdx.x * 8 + (threadIdx.x >> 5);
    int lane = threadIdx.x & 31;
    const float4* xp = reinterpret_cast<const float4*>(x + (size_t)row * DD);
    const float4* wp = reinterpret_cast<const float4*>(w);

    float4 v[4];
    float ss = 0.f;
#pragma unroll
    for (int j = 0; j < 4; j++) {
        v[j] = xp[lane + 32 * j];
        ss += v[j].x * v[j].x + v[j].y * v[j].y + v[j].z * v[j].z + v[j].w * v[j].w;
    }
#pragma unroll
    for (int off = 16; off > 0; off >>= 1)
        ss += __shfl_xor_sync(0xffffffffu, ss, off);

    float r = rsqrtf(ss * (1.0f / DD) + EPSV);

    __half* hb = h16 + (size_t)row * DD;
#pragma unroll
    for (int j = 0; j < 4; j++) {
        float4 wv = wp[lane + 32 * j];
        int col = (lane + 32 * j) * 4;
        __half2* hp = reinterpret_cast<__half2*>(hb + col);
        hp[0] = __floats2half2_rn(v[j].x * r * wv.x, v[j].y * r * wv.y);
        hp[1] = __floats2half2_rn(v[j].z * r * wv.z, v[j].w * r * wv.w);
    }
}

// ---------------- fp32 -> fp16 hi/lo converter (weights) ----------------
__global__ __launch_bounds__(256) void cvt_split_kernel(
    const float* __restrict__ src, __half* __restrict__ hi,
    __half* __restrict__ lo, int n)
{
    int i = blockIdx.x * 256 + threadIdx.x;
    if (i < n) {
        float v = src[i];
        __half h = __float2half_rn(v);
        hi[i] = h;
        lo[i] = __float2half_rn(v - __half2float(h));
    }
}

// ---------------- HMMA fp16 2-product GEMM with ldmatrix ----------------
// A: [M,K] fp16 K-major (single).  B (hi/lo): [N,K] fp16 K-major.
// C = A @ (Bh+Bl)^T (+res). Block 128x128, BK=32, 8 warps (2x4), warp 64x32.
// SMEM row stride = 40 halves (80B): 16B-aligned cp.async + conflict-free LDSM.

#define RS 40                       // halves per smem row
#define TILE_H (128 * RS)           // halves per tile (5120)
#define TB (TILE_H * 2)             // bytes per tile (10240)
#define STAGE_H (3 * TILE_H)        // halves per stage
#define STAGE_B (STAGE_H * 2)       // bytes per stage (30720)
#define GEMM_SMEM_BYTES (2 * STAGE_B)   // 61440

#define MMA_F16(c, a, b)                                                \
    asm volatile(                                                       \
        "mma.sync.aligned.m16n8k16.row.col.f32.f16.f16.f32 "            \
        "{%0,%1,%2,%3}, {%4,%5,%6,%7}, {%8,%9}, {%0,%1,%2,%3};"         \
        : "+f"((c)[0]), "+f"((c)[1]), "+f"((c)[2]), "+f"((c)[3])        \
        : "r"((a)[0]), "r"((a)[1]), "r"((a)[2]), "r"((a)[3]),           \
          "r"((b)[0]), "r"((b)[1]))

#define LDSM4(r0, r1, r2, r3, addr)                                     \
    asm volatile("ldmatrix.sync.aligned.m8n8.x4.shared.b16 "            \
                 "{%0,%1,%2,%3}, [%4];"                                 \
                 : "=r"(r0), "=r"(r1), "=r"(r2), "=r"(r3) : "r"(addr))

__global__ __launch_bounds__(256, 2) void gemm_f16x2(
    const __half* __restrict__ A,
    const __half* __restrict__ Bh, const __half* __restrict__ Bl,
    float* __restrict__ C, const float* __restrict__ res, int N, int K)
{
    extern __shared__ uint16_t sm[];

    const int tid  = threadIdx.x;
    const int lane = tid & 31;
    const int wid  = tid >> 5;
    const int wm   = wid >> 2;        // 0..1 -> m offset wm*64
    const int wn   = wid & 3;         // 0..3 -> n offset wn*32
    const int r    = lane >> 2;       // 0..7
    const int cp   = (lane & 3) * 2;  // 0,2,4,6

    const size_t mBase = (size_t)blockIdx.y * 128;
    const size_t nBase = (size_t)blockIdx.x * 128;

    const __half* srcs[3] = { A + mBase * K, Bh + nBase * K, Bl + nBase * K };

    const uint32_t smem_base = smem_u32(sm);

    // ldmatrix per-lane byte offsets (within a tile)
    const uint32_t aLaneOff =
        (uint32_t)(((wm * 64 + ((lane >> 3) & 1) * 8 + (lane & 7)) * RS
                    + (lane >> 4) * 8) * 2);
    const uint32_t bLaneOff =
        (uint32_t)(((wn * 32 + ((lane >> 4) & 1) * 8 + (lane & 7)) * RS
                    + ((lane >> 3) & 1) * 8) * 2);

    // ---- async stage loader: 3 tiles of 128 rows x 32 halves ----
    auto load_stage = [&](int s, int kt) {
        uint32_t sb = smem_base + (uint32_t)s * STAGE_B;
#pragma unroll
        for (int t = 0; t < 3; t++) {
            const __half* src = srcs[t];
#pragma unroll
            for (int rep = 0; rep < 2; rep++) {
                int o   = tid + rep * 256;      // 0..511
                int row = o >> 2;
                int seg = o & 3;
                uint32_t dst = sb + (uint32_t)t * TB + row * (RS * 2) + seg * 16;
                const void* g = src + (size_t)row * K + kt * 32 + seg * 8;
                asm volatile("cp.async.cg.shared.global [%0], [%1], 16;"
                             :: "r"(dst), "l"(g));
            }
        }
        asm volatile("cp.async.commit_group;" ::: "memory");
    };

    float acc[4][4][4];
#pragma unroll
    for (int i = 0; i < 4; i++)
#pragma unroll
        for (int j = 0; j < 4; j++)
#pragma unroll
            for (int q = 0; q < 4; q++) acc[i][j][q] = 0.f;

    const int nkt = K >> 5;

    load_stage(0, 0);

    for (int kt = 0; kt < nkt; kt++) {
        if (kt + 1 < nkt) {
            load_stage((kt + 1) & 1, kt + 1);
            asm volatile("cp.async.wait_group 1;" ::: "memory");
        } else {
            asm volatile("cp.async.wait_group 0;" ::: "memory");
        }
        __syncthreads();

        uint32_t sb = smem_base + (uint32_t)(kt & 1) * STAGE_B;

#pragma unroll
        for (int k16 = 0; k16 < 32; k16 += 16) {
            uint32_t bh[4][2], bl[4][2];
#pragma unroll
            for (int j = 0; j < 2; j++) {
                uint32_t ad = sb + TB + bLaneOff
                            + (uint32_t)((j * 16 * RS + k16) * 2);
                LDSM4(bh[2*j][0], bh[2*j][1], bh[2*j+1][0], bh[2*j+1][1], ad);
                LDSM4(bl[2*j][0], bl[2*j][1], bl[2*j+1][0], bl[2*j+1][1], ad + TB);
            }
#pragma unroll
            for (int mi = 0; mi < 4; mi++) {
                uint32_t a4[4];
                uint32_t ad = sb + aLaneOff + (uint32_t)((mi * 16 * RS + k16) * 2);
                LDSM4(a4[0], a4[1], a4[2], a4[3], ad);
#pragma unroll
                for (int ni = 0; ni < 4; ni++) {
                    MMA_F16(acc[mi][ni], a4, bh[ni]);
                    MMA_F16(acc[mi][ni], a4, bl[ni]);
                }
            }
        }
        __syncthreads();
    }

    // ---- epilogue ----
#pragma unroll
    for (int mi = 0; mi < 4; mi++) {
        size_t row0 = mBase + wm * 64 + mi * 16 + r;
#pragma unroll
        for (int ni = 0; ni < 4; ni++) {
            size_t col = nBase + wn * 32 + ni * 8 + cp;
            float2 v0 = make_float2(acc[mi][ni][0], acc[mi][ni][1]);
            float2 v1 = make_float2(acc[mi][ni][2], acc[mi][ni][3]);
            if (res) {
                float2 r0 = *reinterpret_cast<const float2*>(res + row0 * N + col);
                float2 r1 = *reinterpret_cast<const float2*>(res + (row0 + 8) * N + col);
                v0.x += r0.x; v0.y += r0.y;
                v1.x += r1.x; v1.y += r1.y;
            }
            *reinterpret_cast<float2*>(C + row0 * N + col) = v0;
            *reinterpret_cast<float2*>(C + (row0 + 8) * N + col) = v1;
        }
    }
}

// ---------------- chunked parallel scan: pass 1 (chunk-local states) --------
__global__ __launch_bounds__(256) void scan_state_kernel(
    const float* __restrict__ a,
    const float* __restrict__ conv_w, const float* __restrict__ conv_b,
    const float* __restrict__ alpha, const float* __restrict__ beta,
    float* __restrict__ S)
{
    int idx = blockIdx.x * 256 + threadIdx.x;   // 0 .. B*NC*INNER-1
    int i = idx & (INNER - 1);
    int c = (idx >> 10) & (NC - 1);
    int b = idx >> 13;

    float w0 = conv_w[i * KW + 0];
    float w1 = conv_w[i * KW + 1];
    float w2 = conv_w[i * KW + 2];
    float w3 = conv_w[i * KW + 3];
    float w4 = conv_w[i * KW + 4];
    float cb = conv_b[i];
    float asig = 1.0f / (1.0f + __expf(-alpha[i]));
    float bt = beta[i];

    const float* col = a + (size_t)b * KK * INNER + i;
    int k0 = c * CL;

    float xm2 = (c > 0) ? col[(size_t)(k0 - 2) * INNER] : 0.f;
    float xm1 = (c > 0) ? col[(size_t)(k0 - 1) * INNER] : 0.f;
    float x0 = col[(size_t)k0 * INNER];
    float x1 = col[(size_t)(k0 + 1) * INNER];
    float s = 0.f;

    for (int k = 0; k < CL; k += 4) {
        float xn[4];
#pragma unroll
        for (int j = 0; j < 4; j++) {
            int kk = k0 + k + 2 + j;
            xn[j] = (kk < KK) ? col[(size_t)kk * INNER] : 0.f;
        }
#pragma unroll
        for (int j = 0; j < 4; j++) {
            float x2 = xn[j];
            float cc = fmaf(w0, xm2, fmaf(w1, xm1, fmaf(w2, x0, fmaf(w3, x1, fmaf(w4, x2, cb)))));
            float u = cc / (1.0f + __expf(-cc));
            s = fmaf(asig, s, bt * u);
            xm2 = xm1; xm1 = x0; x0 = x1; x1 = x2;
        }
    }
    S[((size_t)b * NC + c) * INNER + i] = s;
}

// ---------------- scan pass 2: prefix of chunk states ----------------
__global__ __launch_bounds__(256) void scan_prefix_kernel(
    const float* __restrict__ S, const float* __restrict__ alpha,
    float* __restrict__ Sin)
{
    int idx = blockIdx.x * 256 + threadIdx.x;   // 0 .. B*INNER-1
    int i = idx & (INNER - 1);
    int b = idx >> 10;

    float a = 1.0f / (1.0f + __expf(-alpha[i]));
    float aL = a;
#pragma unroll
    for (int q = 0; q < 8; q++) aL *= aL;       // a^256

    float s = 0.f;
#pragma unroll
    for (int c = 0; c < NC; c++) {
        size_t o = ((size_t)b * NC + c) * INNER + i;
        Sin[o] = s;
        s = fmaf(aL, s, S[o]);
    }
}

// ---------------- scan pass 3: apply (conv+silu+scan+gate -> fp16) ----------
__global__ __launch_bounds__(256) void scan_apply_kernel(
    const float* __restrict__ a, const float* __restrict__ bg,
    const float* __restrict__ Sin,
    __half* __restrict__ g16,
    const float* __restrict__ conv_w, const float* __restrict__ conv_b,
    const float* __restrict__ alpha, const float* __restrict__ beta,
    const float* __restrict__ gamma, const float* __restrict__ delta)
{
    int idx = blockIdx.x * 256 + threadIdx.x;   // 0 .. B*NC*INNER-1
    int i = idx & (INNER - 1);
    int c = (idx >> 10) & (NC - 1);
    int b = idx >> 13;

    float w0 = conv_w[i * KW + 0];
    float w1 = conv_w[i * KW + 1];
    float w2 = conv_w[i * KW + 2];
    float w3 = conv_w[i * KW + 3];
    float w4 = conv_w[i * KW + 4];
    float cb = conv_b[i];
    float asig = 1.0f / (1.0f + __expf(-alpha[i]));
    float bt = beta[i], gm = gamma[i], dl = delta[i];

    const float* col = a  + (size_t)b * KK * INNER + i;
    const float* bp  = bg + (size_t)b * KK * INNER + i;
    __half* gp = g16 + (size_t)b * KK * INNER + i;
    int k0 = c * CL;

    float xm2 = (c > 0) ? col[(size_t)(k0 - 2) * INNER] : 0.f;
    float xm1 = (c > 0) ? col[(size_t)(k0 - 1) * INNER] : 0.f;
    float x0 = col[(size_t)k0 * INNER];
    float x1 = col[(size_t)(k0 + 1) * INNER];
    float s = Sin[((size_t)b * NC + c) * INNER + i];

    for (int k = 0; k < CL; k += 4) {
        float xn[4], bb[4];
#pragma unroll
        for (int j = 0; j < 4; j++) {
            int kk = k0 + k + 2 + j;
            xn[j] = (kk < KK) ? col[(size_t)kk * INNER] : 0.f;
        }
#pragma unroll
        for (int j = 0; j < 4; j++)
            bb[j] = bp[(size_t)(k0 + k + j) * INNER];
#pragma unroll
        for (int j = 0; j < 4; j++) {
            float x2 = xn[j];
            float cc = fmaf(w0, xm2, fmaf(w1, xm1, fmaf(w2, x0, fmaf(w3, x1, fmaf(w4, x2, cb)))));
            float u = cc / (1.0f + __expf(-cc));
            s = fmaf(asig, s, bt * u);
            float y = fmaf(gm, s, dl * u);
            gp[(size_t)(k0 + k + j) * INNER] = __float2half_rn(y * bb[j]);
            xm2 = xm1; xm1 = x0; x0 = x1; x1 = x2;
        }
    }
}

// ---------------- launch ----------------
extern "C" void kernel_launch(void* const* d_in, const int* in_sizes, int n_in,
                              void* d_out, int out_size)
{
    const float* x      = (const float*)d_in[0];
    const float* norm_w = (const float*)d_in[1];
    const float* Wa     = (const float*)d_in[2];
    const float* Wb     = (const float*)d_in[3];
    const float* conv_w = (const float*)d_in[4];
    const float* conv_b = (const float*)d_in[5];
    const float* alpha  = (const float*)d_in[6];
    const float* beta   = (const float*)d_in[7];
    const float* gamma  = (const float*)d_in[8];
    const float* delta  = (const float*)d_in[9];
    const float* Wout   = (const float*)d_in[10];
    float* out = (float*)d_out;

    float *a, *bg, *st, *sin;
    __half *h16, *g16, *wah, *wal, *wbh, *wbl, *woh, *wol;
    cudaGetSymbolAddress((void**)&a,   g_a);
    cudaGetSymbolAddress((void**)&bg,  g_bg);
    cudaGetSymbolAddress((void**)&st,  g_state);
    cudaGetSymbolAddress((void**)&sin, g_sin);
    cudaGetSymbolAddress((void**)&h16, g_h16);
    cudaGetSymbolAddress((void**)&g16, g_g16);
    cudaGetSymbolAddress((void**)&wah, g_wah);
    cudaGetSymbolAddress((void**)&wal, g_wal);
    cudaGetSymbolAddress((void**)&wbh, g_wbh);
    cudaGetSymbolAddress((void**)&wbl, g_wbl);
    cudaGetSymbolAddress((void**)&woh, g_woh);
    cudaGetSymbolAddress((void**)&wol, g_wol);

    cudaFuncSetAttribute(gemm_f16x2,
                         cudaFuncAttributeMaxDynamicSharedMemorySize, GEMM_SMEM_BYTES);

    // 1) rmsnorm -> fp16
    rmsnorm_kernel<<<MM / 8, 256>>>(x, norm_w, h16);

    // 2) weight conversions (fp16 hi/lo)
    cvt_split_kernel<<<(INNER * DD + 255) / 256, 256>>>(Wa,   wah, wal, INNER * DD);
    cvt_split_kernel<<<(INNER * DD + 255) / 256, 256>>>(Wb,   wbh, wbl, INNER * DD);
    cvt_split_kernel<<<(DD * INNER + 255) / 256, 256>>>(Wout, woh, wol, DD * INNER);

    // 3) a = h @ Wa^T, b = h @ Wb^T   (M=32768, N=1024, K=512)
    {
        dim3 grid(INNER / 128, MM / 128);
        gemm_f16x2<<<grid, 256, GEMM_SMEM_BYTES>>>(h16, wah, wal, a,  nullptr, INNER, DD);
        gemm_f16x2<<<grid, 256, GEMM_SMEM_BYTES>>>(h16, wbh, wbl, bg, nullptr, INNER, DD);
    }

    // 4) chunked parallel scan (3 passes)
    scan_state_kernel<<<BB * NC * INNER / 256, 256>>>(a, conv_w, conv_b, alpha, beta, st);
    scan_prefix_kernel<<<BB * INNER / 256, 256>>>(st, alpha, sin);
    scan_apply_kernel<<<BB * NC * INNER / 256, 256>>>(
        a, bg, sin, g16, conv_w, conv_b, alpha, beta, gamma, delta);

    // 5) out = x + g @ Wout^T   (M=32768, N=512, K=1024)
    {
        dim3 grid(DD / 128, MM / 128);
        gemm_f16x2<<<grid, 256, GEMM_SMEM_BYTES>>>(g16, woh, wol, out, x, DD, INNER);
    }
}

// round 7
// speedup vs baseline: 6.9702x; 1.3792x over previous
#include <cuda_runtime.h>
#include <cuda_fp16.h>
#include <cstdint>

// ---------------- problem constants ----------------
#define BB    16
#define KK    2048
#define DD    512
#define INNER 1024
#define KW    5
#define MM    (BB*KK)      // 32768
#define EPSV  1e-5f
#define NC    8            // scan chunks
#define CL    (KK/NC)      // 256

// ---------------- scratch (device globals) ----------------
__device__ float   g_a [(size_t)MM * INNER];   // conv input (fp32)
__device__ float   g_bg[(size_t)MM * INNER];   // b gate     (fp32)
__device__ __half  g_h16[(size_t)MM * DD];     // rmsnorm out (fp16)
__device__ __half  g_g16[(size_t)MM * INNER];  // scan out    (fp16)
__device__ __half  g_wa16[INNER * DD];
__device__ __half  g_wb16[INNER * DD];
__device__ __half  g_wo16[DD * INNER];
__device__ float   g_state[BB * NC * INNER];   // chunk-local final states
__device__ float   g_sin  [BB * NC * INNER];   // carried-in states

__device__ __forceinline__ uint32_t smem_u32(const void* p) {
    uint32_t a;
    asm("{ .reg .u64 t; cvta.to.shared.u64 t, %1; cvt.u32.u64 %0, t; }"
        : "=r"(a) : "l"(p));
    return a;
}

// ---------------- rmsnorm -> fp16 ----------------
__global__ __launch_bounds__(256) void rmsnorm_kernel(
    const float* __restrict__ x, const float* __restrict__ w,
    __half* __restrict__ h16)
{
    int row  = blockIdx.x * 8 + (threadIdx.x >> 5);
    int lane = threadIdx.x & 31;
    const float4* xp = reinterpret_cast<const float4*>(x + (size_t)row * DD);
    const float4* wp = reinterpret_cast<const float4*>(w);

    float4 v[4];
    float ss = 0.f;
#pragma unroll
    for (int j = 0; j < 4; j++) {
        v[j] = xp[lane + 32 * j];
        ss += v[j].x * v[j].x + v[j].y * v[j].y + v[j].z * v[j].z + v[j].w * v[j].w;
    }
#pragma unroll
    for (int off = 16; off > 0; off >>= 1)
        ss += __shfl_xor_sync(0xffffffffu, ss, off);

    float r = rsqrtf(ss * (1.0f / DD) + EPSV);

    __half* hb = h16 + (size_t)row * DD;
#pragma unroll
    for (int j = 0; j < 4; j++) {
        float4 wv = wp[lane + 32 * j];
        int col = (lane + 32 * j) * 4;
        __half2* hp = reinterpret_cast<__half2*>(hb + col);
        hp[0] = __floats2half2_rn(v[j].x * r * wv.x, v[j].y * r * wv.y);
        hp[1] = __floats2half2_rn(v[j].z * r * wv.z, v[j].w * r * wv.w);
    }
}

// ---------------- fp32 -> fp16 cast (weights) ----------------
__global__ __launch_bounds__(256) void cvt_kernel(
    const float* __restrict__ src, __half* __restrict__ dst, int n)
{
    int i = blockIdx.x * 256 + threadIdx.x;
    if (i < n) dst[i] = __float2half_rn(src[i]);
}

// ---------------- HMMA fp16 GEMM with ldmatrix, 3-stage pipeline ------------
// A: [M,K] fp16 K-major.  B: [N,K] fp16 K-major.  C = A@B^T (+res), fp32 out.
// Block 128x128, BK=32, 8 warps (2x4), warp tile 64x32.
// SMEM row stride = 40 halves (80B): 16B-aligned cp.async + conflict-free LDSM.

#define RS 40                       // halves per smem row
#define TILE_H (128 * RS)           // halves per tile (5120)
#define TB (TILE_H * 2)             // bytes per tile (10240)
#define STAGE_B (2 * TB)            // bytes per stage (20480)
#define NSTAGE 3
#define GEMM_SMEM_BYTES (NSTAGE * STAGE_B)   // 61440

#define MMA_F16(c, a, b)                                                \
    asm volatile(                                                       \
        "mma.sync.aligned.m16n8k16.row.col.f32.f16.f16.f32 "            \
        "{%0,%1,%2,%3}, {%4,%5,%6,%7}, {%8,%9}, {%0,%1,%2,%3};"         \
        : "+f"((c)[0]), "+f"((c)[1]), "+f"((c)[2]), "+f"((c)[3])        \
        : "r"((a)[0]), "r"((a)[1]), "r"((a)[2]), "r"((a)[3]),           \
          "r"((b)[0]), "r"((b)[1]))

#define LDSM4(r0, r1, r2, r3, addr)                                     \
    asm volatile("ldmatrix.sync.aligned.m8n8.x4.shared.b16 "            \
                 "{%0,%1,%2,%3}, [%4];"                                 \
                 : "=r"(r0), "=r"(r1), "=r"(r2), "=r"(r3) : "r"(addr))

__global__ __launch_bounds__(256, 2) void gemm_f16(
    const __half* __restrict__ A, const __half* __restrict__ B,
    float* __restrict__ C, const float* __restrict__ res, int N, int K)
{
    extern __shared__ uint16_t sm[];

    const int tid  = threadIdx.x;
    const int lane = tid & 31;
    const int wid  = tid >> 5;
    const int wm   = wid >> 2;        // 0..1 -> m offset wm*64
    const int wn   = wid & 3;         // 0..3 -> n offset wn*32
    const int r    = lane >> 2;       // 0..7
    const int cp   = (lane & 3) * 2;  // 0,2,4,6

    const size_t mBase = (size_t)blockIdx.y * 128;
    const size_t nBase = (size_t)blockIdx.x * 128;

    const __half* srcA = A + mBase * K;
    const __half* srcB = B + nBase * K;

    const uint32_t smem_base = smem_u32(sm);

    // ldmatrix per-lane byte offsets (within a tile)
    const uint32_t aLaneOff =
        (uint32_t)(((wm * 64 + ((lane >> 3) & 1) * 8 + (lane & 7)) * RS
                    + (lane >> 4) * 8) * 2);
    const uint32_t bLaneOff =
        (uint32_t)(((wn * 32 + ((lane >> 4) & 1) * 8 + (lane & 7)) * RS
                    + ((lane >> 3) & 1) * 8) * 2);

    // per-thread load slot: 2 x 16B per tile
    const int lrow0 = tid >> 2;          // 0..63
    const int lseg  = tid & 3;           // 0..3
    // ---- async stage loader: 2 tiles of 128 rows x 32 halves ----
    auto load_stage = [&](int s, int kt) {
        uint32_t sb = smem_base + (uint32_t)s * STAGE_B;
#pragma unroll
        for (int rep = 0; rep < 2; rep++) {
            int row = lrow0 + rep * 64;
            uint32_t off = row * (RS * 2) + lseg * 16;
            size_t go = (size_t)row * K + kt * 32 + lseg * 8;
            asm volatile("cp.async.cg.shared.global [%0], [%1], 16;"
                         :: "r"(sb + off), "l"(srcA + go));
            asm volatile("cp.async.cg.shared.global [%0], [%1], 16;"
                         :: "r"(sb + TB + off), "l"(srcB + go));
        }
        asm volatile("cp.async.commit_group;" ::: "memory");
    };

    float acc[4][4][4];
#pragma unroll
    for (int i = 0; i < 4; i++)
#pragma unroll
        for (int j = 0; j < 4; j++)
#pragma unroll
            for (int q = 0; q < 4; q++) acc[i][j][q] = 0.f;

    const int nkt = K >> 5;

    load_stage(0, 0);
    load_stage(1, 1);

    int sc = 0;                          // stage index of kt (kt % 3)
    for (int kt = 0; kt < nkt; kt++) {
        if (kt + 1 < nkt) {
            asm volatile("cp.async.wait_group 1;" ::: "memory");
        } else {
            asm volatile("cp.async.wait_group 0;" ::: "memory");
        }
        __syncthreads();

        if (kt + 2 < nkt) {
            int s2 = sc + 2; if (s2 >= NSTAGE) s2 -= NSTAGE;
            load_stage(s2, kt + 2);
        }

        uint32_t sb = smem_base + (uint32_t)sc * STAGE_B;

#pragma unroll
        for (int k16 = 0; k16 < 32; k16 += 16) {
            uint32_t bh[4][2];
#pragma unroll
            for (int j = 0; j < 2; j++) {
                uint32_t ad = sb + TB + bLaneOff
                            + (uint32_t)((j * 16 * RS + k16) * 2);
                LDSM4(bh[2*j][0], bh[2*j][1], bh[2*j+1][0], bh[2*j+1][1], ad);
            }
#pragma unroll
            for (int mi = 0; mi < 4; mi++) {
                uint32_t a4[4];
                uint32_t ad = sb + aLaneOff + (uint32_t)((mi * 16 * RS + k16) * 2);
                LDSM4(a4[0], a4[1], a4[2], a4[3], ad);
#pragma unroll
                for (int ni = 0; ni < 4; ni++)
                    MMA_F16(acc[mi][ni], a4, bh[ni]);
            }
        }
        __syncthreads();
        if (++sc == NSTAGE) sc = 0;
    }

    // ---- epilogue ----
#pragma unroll
    for (int mi = 0; mi < 4; mi++) {
        size_t row0 = mBase + wm * 64 + mi * 16 + r;
#pragma unroll
        for (int ni = 0; ni < 4; ni++) {
            size_t col = nBase + wn * 32 + ni * 8 + cp;
            float2 v0 = make_float2(acc[mi][ni][0], acc[mi][ni][1]);
            float2 v1 = make_float2(acc[mi][ni][2], acc[mi][ni][3]);
            if (res) {
                float2 r0 = *reinterpret_cast<const float2*>(res + row0 * N + col);
                float2 r1 = *reinterpret_cast<const float2*>(res + (row0 + 8) * N + col);
                v0.x += r0.x; v0.y += r0.y;
                v1.x += r1.x; v1.y += r1.y;
            }
            *reinterpret_cast<float2*>(C + row0 * N + col) = v0;
            *reinterpret_cast<float2*>(C + (row0 + 8) * N + col) = v1;
        }
    }
}

// ---------------- chunked parallel scan: pass 1 (chunk-local states) --------
__global__ __launch_bounds__(256) void scan_state_kernel(
    const float* __restrict__ a,
    const float* __restrict__ conv_w, const float* __restrict__ conv_b,
    const float* __restrict__ alpha, const float* __restrict__ beta,
    float* __restrict__ S)
{
    int idx = blockIdx.x * 256 + threadIdx.x;   // 0 .. B*NC*INNER-1
    int i = idx & (INNER - 1);
    int c = (idx >> 10) & (NC - 1);
    int b = idx >> 13;

    float w0 = conv_w[i * KW + 0];
    float w1 = conv_w[i * KW + 1];
    float w2 = conv_w[i * KW + 2];
    float w3 = conv_w[i * KW + 3];
    float w4 = conv_w[i * KW + 4];
    float cb = conv_b[i];
    float asig = 1.0f / (1.0f + __expf(-alpha[i]));
    float bt = beta[i];

    const float* col = a + (size_t)b * KK * INNER + i;
    int k0 = c * CL;

    float xm2 = (c > 0) ? col[(size_t)(k0 - 2) * INNER] : 0.f;
    float xm1 = (c > 0) ? col[(size_t)(k0 - 1) * INNER] : 0.f;
    float x0 = col[(size_t)k0 * INNER];
    float x1 = col[(size_t)(k0 + 1) * INNER];
    float s = 0.f;

    for (int k = 0; k < CL; k += 4) {
        float xn[4];
#pragma unroll
        for (int j = 0; j < 4; j++) {
            int kk = k0 + k + 2 + j;
            xn[j] = (kk < KK) ? col[(size_t)kk * INNER] : 0.f;
        }
#pragma unroll
        for (int j = 0; j < 4; j++) {
            float x2 = xn[j];
            float cc = fmaf(w0, xm2, fmaf(w1, xm1, fmaf(w2, x0, fmaf(w3, x1, fmaf(w4, x2, cb)))));
            float u = cc / (1.0f + __expf(-cc));
            s = fmaf(asig, s, bt * u);
            xm2 = xm1; xm1 = x0; x0 = x1; x1 = x2;
        }
    }
    S[((size_t)b * NC + c) * INNER + i] = s;
}

// ---------------- scan pass 2: prefix of chunk states ----------------
__global__ __launch_bounds__(256) void scan_prefix_kernel(
    const float* __restrict__ S, const float* __restrict__ alpha,
    float* __restrict__ Sin)
{
    int idx = blockIdx.x * 256 + threadIdx.x;   // 0 .. B*INNER-1
    int i = idx & (INNER - 1);
    int b = idx >> 10;

    float a = 1.0f / (1.0f + __expf(-alpha[i]));
    float aL = a;
#pragma unroll
    for (int q = 0; q < 8; q++) aL *= aL;       // a^256

    float s = 0.f;
#pragma unroll
    for (int c = 0; c < NC; c++) {
        size_t o = ((size_t)b * NC + c) * INNER + i;
        Sin[o] = s;
        s = fmaf(aL, s, S[o]);
    }
}

// ---------------- scan pass 3: apply (conv+silu+scan+gate -> fp16) ----------
__global__ __launch_bounds__(256) void scan_apply_kernel(
    const float* __restrict__ a, const float* __restrict__ bg,
    const float* __restrict__ Sin,
    __half* __restrict__ g16,
    const float* __restrict__ conv_w, const float* __restrict__ conv_b,
    const float* __restrict__ alpha, const float* __restrict__ beta,
    const float* __restrict__ gamma, const float* __restrict__ delta)
{
    int idx = blockIdx.x * 256 + threadIdx.x;   // 0 .. B*NC*INNER-1
    int i = idx & (INNER - 1);
    int c = (idx >> 10) & (NC - 1);
    int b = idx >> 13;

    float w0 = conv_w[i * KW + 0];
    float w1 = conv_w[i * KW + 1];
    float w2 = conv_w[i * KW + 2];
    float w3 = conv_w[i * KW + 3];
    float w4 = conv_w[i * KW + 4];
    float cb = conv_b[i];
    float asig = 1.0f / (1.0f + __expf(-alpha[i]));
    float bt = beta[i], gm = gamma[i], dl = delta[i];

    const float* col = a  + (size_t)b * KK * INNER + i;
    const float* bp  = bg + (size_t)b * KK * INNER + i;
    __half* gp = g16 + (size_t)b * KK * INNER + i;
    int k0 = c * CL;

    float xm2 = (c > 0) ? col[(size_t)(k0 - 2) * INNER] : 0.f;
    float xm1 = (c > 0) ? col[(size_t)(k0 - 1) * INNER] : 0.f;
    float x0 = col[(size_t)k0 * INNER];
    float x1 = col[(size_t)(k0 + 1) * INNER];
    float s = Sin[((size_t)b * NC + c) * INNER + i];

    for (int k = 0; k < CL; k += 4) {
        float xn[4], bb[4];
#pragma unroll
        for (int j = 0; j < 4; j++) {
            int kk = k0 + k + 2 + j;
            xn[j] = (kk < KK) ? col[(size_t)kk * INNER] : 0.f;
        }
#pragma unroll
        for (int j = 0; j < 4; j++)
            bb[j] = bp[(size_t)(k0 + k + j) * INNER];
#pragma unroll
        for (int j = 0; j < 4; j++) {
            float x2 = xn[j];
            float cc = fmaf(w0, xm2, fmaf(w1, xm1, fmaf(w2, x0, fmaf(w3, x1, fmaf(w4, x2, cb)))));
            float u = cc / (1.0f + __expf(-cc));
            s = fmaf(asig, s, bt * u);
            float y = fmaf(gm, s, dl * u);
            gp[(size_t)(k0 + k + j) * INNER] = __float2half_rn(y * bb[j]);
            xm2 = xm1; xm1 = x0; x0 = x1; x1 = x2;
        }
    }
}

// ---------------- launch ----------------
extern "C" void kernel_launch(void* const* d_in, const int* in_sizes, int n_in,
                              void* d_out, int out_size)
{
    const float* x      = (const float*)d_in[0];
    const float* norm_w = (const float*)d_in[1];
    const float* Wa     = (const float*)d_in[2];
    const float* Wb     = (const float*)d_in[3];
    const float* conv_w = (const float*)d_in[4];
    const float* conv_b = (const float*)d_in[5];
    const float* alpha  = (const float*)d_in[6];
    const float* beta   = (const float*)d_in[7];
    const float* gamma  = (const float*)d_in[8];
    const float* delta  = (const float*)d_in[9];
    const float* Wout   = (const float*)d_in[10];
    float* out = (float*)d_out;

    float *a, *bg, *st, *sin;
    __half *h16, *g16, *wa16, *wb16, *wo16;
    cudaGetSymbolAddress((void**)&a,    g_a);
    cudaGetSymbolAddress((void**)&bg,   g_bg);
    cudaGetSymbolAddress((void**)&st,   g_state);
    cudaGetSymbolAddress((void**)&sin,  g_sin);
    cudaGetSymbolAddress((void**)&h16,  g_h16);
    cudaGetSymbolAddress((void**)&g16,  g_g16);
    cudaGetSymbolAddress((void**)&wa16, g_wa16);
    cudaGetSymbolAddress((void**)&wb16, g_wb16);
    cudaGetSymbolAddress((void**)&wo16, g_wo16);

    cudaFuncSetAttribute(gemm_f16,
                         cudaFuncAttributeMaxDynamicSharedMemorySize, GEMM_SMEM_BYTES);

    // 1) rmsnorm -> fp16
    rmsnorm_kernel<<<MM / 8, 256>>>(x, norm_w, h16);

    // 2) weight conversions (fp16)
    cvt_kernel<<<(INNER * DD + 255) / 256, 256>>>(Wa,   wa16, INNER * DD);
    cvt_kernel<<<(INNER * DD + 255) / 256, 256>>>(Wb,   wb16, INNER * DD);
    cvt_kernel<<<(DD * INNER + 255) / 256, 256>>>(Wout, wo16, DD * INNER);

    // 3) a = h @ Wa^T, b = h @ Wb^T   (M=32768, N=1024, K=512)
    {
        dim3 grid(INNER / 128, MM / 128);
        gemm_f16<<<grid, 256, GEMM_SMEM_BYTES>>>(h16, wa16, a,  nullptr, INNER, DD);
        gemm_f16<<<grid, 256, GEMM_SMEM_BYTES>>>(h16, wb16, bg, nullptr, INNER, DD);
    }

    // 4) chunked parallel scan (3 passes)
    scan_state_kernel<<<BB * NC * INNER / 256, 256>>>(a, conv_w, conv_b, alpha, beta, st);
    scan_prefix_kernel<<<BB * INNER / 256, 256>>>(st, alpha, sin);
    scan_apply_kernel<<<BB * NC * INNER / 256, 256>>>(
        a, bg, sin, g16, conv_w, conv_b, alpha, beta, gamma, delta);

    // 5) out = x + g @ Wout^T   (M=32768, N=512, K=1024)
    {
        dim3 grid(DD / 128, MM / 128);
        gemm_f16<<<grid, 256, GEMM_SMEM_BYTES>>>(g16, wo16, out, x, DD, INNER);
    }
}

// round 8
// speedup vs baseline: 7.2796x; 1.0444x over previous
#include <cuda_runtime.h>
#include <cuda_fp16.h>
#include <cstdint>

// ---------------- problem constants ----------------
#define BB    16
#define KK    2048
#define DD    512
#define INNER 1024
#define W2    (2*INNER)    // combined a|b row stride
#define KW    5
#define MM    (BB*KK)      // 32768
#define EPSV  1e-5f
#define NC    8            // scan chunks
#define CL    (KK/NC)      // 256

// ---------------- scratch (device globals) ----------------
__device__ __half  g_ab [(size_t)MM * W2];     // [M, 2048]: a | b (fp16) 128MB
__device__ __half  g_h16[(size_t)MM * DD];     // rmsnorm out (fp16)
__device__ __half  g_g16[(size_t)MM * INNER];  // scan out    (fp16)
__device__ __half  g_w2 [W2 * DD];             // [Wa;Wb] fp16
__device__ __half  g_wo16[DD * INNER];
__device__ float   g_state[BB * NC * INNER];   // chunk-local final states
__device__ float   g_sin  [BB * NC * INNER];   // carried-in states

__device__ __forceinline__ uint32_t smem_u32(const void* p) {
    uint32_t a;
    asm("{ .reg .u64 t; cvta.to.shared.u64 t, %1; cvt.u32.u64 %0, t; }"
        : "=r"(a) : "l"(p));
    return a;
}

// ---------------- rmsnorm -> fp16 ----------------
__global__ __launch_bounds__(256) void rmsnorm_kernel(
    const float* __restrict__ x, const float* __restrict__ w,
    __half* __restrict__ h16)
{
    int row  = blockIdx.x * 8 + (threadIdx.x >> 5);
    int lane = threadIdx.x & 31;
    const float4* xp = reinterpret_cast<const float4*>(x + (size_t)row * DD);
    const float4* wp = reinterpret_cast<const float4*>(w);

    float4 v[4];
    float ss = 0.f;
#pragma unroll
    for (int j = 0; j < 4; j++) {
        v[j] = xp[lane + 32 * j];
        ss += v[j].x * v[j].x + v[j].y * v[j].y + v[j].z * v[j].z + v[j].w * v[j].w;
    }
#pragma unroll
    for (int off = 16; off > 0; off >>= 1)
        ss += __shfl_xor_sync(0xffffffffu, ss, off);

    float r = rsqrtf(ss * (1.0f / DD) + EPSV);

    __half* hb = h16 + (size_t)row * DD;
#pragma unroll
    for (int j = 0; j < 4; j++) {
        float4 wv = wp[lane + 32 * j];
        int col = (lane + 32 * j) * 4;
        __half2* hp = reinterpret_cast<__half2*>(hb + col);
        hp[0] = __floats2half2_rn(v[j].x * r * wv.x, v[j].y * r * wv.y);
        hp[1] = __floats2half2_rn(v[j].z * r * wv.z, v[j].w * r * wv.w);
    }
}

// ---------------- fp32 -> fp16 cast (weights), vectorized ----------------
__global__ __launch_bounds__(256) void cvt_kernel(
    const float* __restrict__ src, __half* __restrict__ dst, int n4)
{
    int i = blockIdx.x * 256 + threadIdx.x;
    if (i < n4) {
        float4 v = reinterpret_cast<const float4*>(src)[i];
        __half2* d = reinterpret_cast<__half2*>(dst) + i * 2;
        d[0] = __floats2half2_rn(v.x, v.y);
        d[1] = __floats2half2_rn(v.z, v.w);
    }
}

// ---------------- HMMA fp16 GEMM with ldmatrix, 3-stage pipeline ------------
// A: [M,K] fp16 K-major.  B: [N,K] fp16 K-major.  C = A@B^T (+res).
// Block 128x128, BK=32, 8 warps (2x4), warp tile 64x32.
// SMEM row stride = 40 halves (80B): 16B-aligned cp.async + conflict-free LDSM.

#define RS 40                       // halves per smem row
#define TILE_H (128 * RS)           // halves per tile (5120)
#define TB (TILE_H * 2)             // bytes per tile (10240)
#define STAGE_B (2 * TB)            // bytes per stage (20480)
#define NSTAGE 3
#define GEMM_SMEM_BYTES (NSTAGE * STAGE_B)   // 61440

#define MMA_F16(c, a, b)                                                \
    asm volatile(                                                       \
        "mma.sync.aligned.m16n8k16.row.col.f32.f16.f16.f32 "            \
        "{%0,%1,%2,%3}, {%4,%5,%6,%7}, {%8,%9}, {%0,%1,%2,%3};"         \
        : "+f"((c)[0]), "+f"((c)[1]), "+f"((c)[2]), "+f"((c)[3])        \
        : "r"((a)[0]), "r"((a)[1]), "r"((a)[2]), "r"((a)[3]),           \
          "r"((b)[0]), "r"((b)[1]))

#define LDSM4(r0, r1, r2, r3, addr)                                     \
    asm volatile("ldmatrix.sync.aligned.m8n8.x4.shared.b16 "            \
                 "{%0,%1,%2,%3}, [%4];"                                 \
                 : "=r"(r0), "=r"(r1), "=r"(r2), "=r"(r3) : "r"(addr))

template <bool HALF_OUT>
__global__ __launch_bounds__(256, 2) void gemm_f16(
    const __half* __restrict__ A, const __half* __restrict__ B,
    void* __restrict__ Cv, const float* __restrict__ res, int N, int K)
{
    extern __shared__ uint16_t sm[];

    const int tid  = threadIdx.x;
    const int lane = tid & 31;
    const int wid  = tid >> 5;
    const int wm   = wid >> 2;        // 0..1 -> m offset wm*64
    const int wn   = wid & 3;         // 0..3 -> n offset wn*32
    const int r    = lane >> 2;       // 0..7
    const int cp   = (lane & 3) * 2;  // 0,2,4,6

    const size_t mBase = (size_t)blockIdx.y * 128;
    const size_t nBase = (size_t)blockIdx.x * 128;

    const __half* srcA = A + mBase * K;
    const __half* srcB = B + nBase * K;

    const uint32_t smem_base = smem_u32(sm);

    const uint32_t aLaneOff =
        (uint32_t)(((wm * 64 + ((lane >> 3) & 1) * 8 + (lane & 7)) * RS
                    + (lane >> 4) * 8) * 2);
    const uint32_t bLaneOff =
        (uint32_t)(((wn * 32 + ((lane >> 4) & 1) * 8 + (lane & 7)) * RS
                    + ((lane >> 3) & 1) * 8) * 2);

    const int lrow0 = tid >> 2;          // 0..63
    const int lseg  = tid & 3;           // 0..3
    auto load_stage = [&](int s, int kt) {
        uint32_t sb = smem_base + (uint32_t)s * STAGE_B;
#pragma unroll
        for (int rep = 0; rep < 2; rep++) {
            int row = lrow0 + rep * 64;
            uint32_t off = row * (RS * 2) + lseg * 16;
            size_t go = (size_t)row * K + kt * 32 + lseg * 8;
            asm volatile("cp.async.cg.shared.global [%0], [%1], 16;"
                         :: "r"(sb + off), "l"(srcA + go));
            asm volatile("cp.async.cg.shared.global [%0], [%1], 16;"
                         :: "r"(sb + TB + off), "l"(srcB + go));
        }
        asm volatile("cp.async.commit_group;" ::: "memory");
    };

    float acc[4][4][4];
#pragma unroll
    for (int i = 0; i < 4; i++)
#pragma unroll
        for (int j = 0; j < 4; j++)
#pragma unroll
            for (int q = 0; q < 4; q++) acc[i][j][q] = 0.f;

    const int nkt = K >> 5;

    load_stage(0, 0);
    load_stage(1, 1);

    int sc = 0;
    for (int kt = 0; kt < nkt; kt++) {
        if (kt + 1 < nkt) {
            asm volatile("cp.async.wait_group 1;" ::: "memory");
        } else {
            asm volatile("cp.async.wait_group 0;" ::: "memory");
        }
        __syncthreads();

        if (kt + 2 < nkt) {
            int s2 = sc + 2; if (s2 >= NSTAGE) s2 -= NSTAGE;
            load_stage(s2, kt + 2);
        }

        uint32_t sb = smem_base + (uint32_t)sc * STAGE_B;

#pragma unroll
        for (int k16 = 0; k16 < 32; k16 += 16) {
            uint32_t bh[4][2];
#pragma unroll
            for (int j = 0; j < 2; j++) {
                uint32_t ad = sb + TB + bLaneOff
                            + (uint32_t)((j * 16 * RS + k16) * 2);
                LDSM4(bh[2*j][0], bh[2*j][1], bh[2*j+1][0], bh[2*j+1][1], ad);
            }
#pragma unroll
            for (int mi = 0; mi < 4; mi++) {
                uint32_t a4[4];
                uint32_t ad = sb + aLaneOff + (uint32_t)((mi * 16 * RS + k16) * 2);
                LDSM4(a4[0], a4[1], a4[2], a4[3], ad);
#pragma unroll
                for (int ni = 0; ni < 4; ni++)
                    MMA_F16(acc[mi][ni], a4, bh[ni]);
            }
        }
        __syncthreads();
        if (++sc == NSTAGE) sc = 0;
    }

    // ---- epilogue ----
#pragma unroll
    for (int mi = 0; mi < 4; mi++) {
        size_t row0 = mBase + wm * 64 + mi * 16 + r;
#pragma unroll
        for (int ni = 0; ni < 4; ni++) {
            size_t col = nBase + wn * 32 + ni * 8 + cp;
            if (HALF_OUT) {
                __half* C = (__half*)Cv;
                *reinterpret_cast<__half2*>(C + row0 * N + col) =
                    __floats2half2_rn(acc[mi][ni][0], acc[mi][ni][1]);
                *reinterpret_cast<__half2*>(C + (row0 + 8) * N + col) =
                    __floats2half2_rn(acc[mi][ni][2], acc[mi][ni][3]);
            } else {
                float* C = (float*)Cv;
                float2 v0 = make_float2(acc[mi][ni][0], acc[mi][ni][1]);
                float2 v1 = make_float2(acc[mi][ni][2], acc[mi][ni][3]);
                if (res) {
                    float2 r0 = *reinterpret_cast<const float2*>(res + row0 * N + col);
                    float2 r1 = *reinterpret_cast<const float2*>(res + (row0 + 8) * N + col);
                    v0.x += r0.x; v0.y += r0.y;
                    v1.x += r1.x; v1.y += r1.y;
                }
                *reinterpret_cast<float2*>(C + row0 * N + col) = v0;
                *reinterpret_cast<float2*>(C + (row0 + 8) * N + col) = v1;
            }
        }
    }
}

// ---------------- chunked parallel scan: pass 1 (chunk-local states) --------
__global__ __launch_bounds__(256) void scan_state_kernel(
    const __half* __restrict__ ab,
    const float* __restrict__ conv_w, const float* __restrict__ conv_b,
    const float* __restrict__ alpha, const float* __restrict__ beta,
    float* __restrict__ S)
{
    int idx = blockIdx.x * 256 + threadIdx.x;   // 0 .. B*NC*INNER-1
    int i = idx & (INNER - 1);
    int c = (idx >> 10) & (NC - 1);
    int b = idx >> 13;

    float w0 = conv_w[i * KW + 0];
    float w1 = conv_w[i * KW + 1];
    float w2 = conv_w[i * KW + 2];
    float w3 = conv_w[i * KW + 3];
    float w4 = conv_w[i * KW + 4];
    float cb = conv_b[i];
    float asig = 1.0f / (1.0f + __expf(-alpha[i]));
    float bt = beta[i];

    const __half* col = ab + (size_t)b * KK * W2 + i;
    int k0 = c * CL;

    float xm2 = (c > 0) ? __half2float(col[(size_t)(k0 - 2) * W2]) : 0.f;
    float xm1 = (c > 0) ? __half2float(col[(size_t)(k0 - 1) * W2]) : 0.f;
    float x0 = __half2float(col[(size_t)k0 * W2]);
    float x1 = __half2float(col[(size_t)(k0 + 1) * W2]);
    float s = 0.f;

    for (int k = 0; k < CL; k += 4) {
        float xn[4];
#pragma unroll
        for (int j = 0; j < 4; j++) {
            int kk = k0 + k + 2 + j;
            xn[j] = (kk < KK) ? __half2float(col[(size_t)kk * W2]) : 0.f;
        }
#pragma unroll
        for (int j = 0; j < 4; j++) {
            float x2 = xn[j];
            float cc = fmaf(w0, xm2, fmaf(w1, xm1, fmaf(w2, x0, fmaf(w3, x1, fmaf(w4, x2, cb)))));
            float u = cc / (1.0f + __expf(-cc));
            s = fmaf(asig, s, bt * u);
            xm2 = xm1; xm1 = x0; x0 = x1; x1 = x2;
        }
    }
    S[((size_t)b * NC + c) * INNER + i] = s;
}

// ---------------- scan pass 2: prefix of chunk states ----------------
__global__ __launch_bounds__(256) void scan_prefix_kernel(
    const float* __restrict__ S, const float* __restrict__ alpha,
    float* __restrict__ Sin)
{
    int idx = blockIdx.x * 256 + threadIdx.x;   // 0 .. B*INNER-1
    int i = idx & (INNER - 1);
    int b = idx >> 10;

    float a = 1.0f / (1.0f + __expf(-alpha[i]));
    float aL = a;
#pragma unroll
    for (int q = 0; q < 8; q++) aL *= aL;       // a^256

    float s = 0.f;
#pragma unroll
    for (int c = 0; c < NC; c++) {
        size_t o = ((size_t)b * NC + c) * INNER + i;
        Sin[o] = s;
        s = fmaf(aL, s, S[o]);
    }
}

// ---------------- scan pass 3: apply (conv+silu+scan+gate -> fp16) ----------
__global__ __launch_bounds__(256) void scan_apply_kernel(
    const __half* __restrict__ ab,
    const float* __restrict__ Sin,
    __half* __restrict__ g16,
    const float* __restrict__ conv_w, const float* __restrict__ conv_b,
    const float* __restrict__ alpha, const float* __restrict__ beta,
    const float* __restrict__ gamma, const float* __restrict__ delta)
{
    int idx = blockIdx.x * 256 + threadIdx.x;   // 0 .. B*NC*INNER-1
    int i = idx & (INNER - 1);
    int c = (idx >> 10) & (NC - 1);
    int b = idx >> 13;

    float w0 = conv_w[i * KW + 0];
    float w1 = conv_w[i * KW + 1];
    float w2 = conv_w[i * KW + 2];
    float w3 = conv_w[i * KW + 3];
    float w4 = conv_w[i * KW + 4];
    float cb = conv_b[i];
    float asig = 1.0f / (1.0f + __expf(-alpha[i]));
    float bt = beta[i], gm = gamma[i], dl = delta[i];

    const __half* col = ab + (size_t)b * KK * W2 + i;
    const __half* bp  = col + INNER;
    __half* gp = g16 + (size_t)b * KK * INNER + i;
    int k0 = c * CL;

    float xm2 = (c > 0) ? __half2float(col[(size_t)(k0 - 2) * W2]) : 0.f;
    float xm1 = (c > 0) ? __half2float(col[(size_t)(k0 - 1) * W2]) : 0.f;
    float x0 = __half2float(col[(size_t)k0 * W2]);
    float x1 = __half2float(col[(size_t)(k0 + 1) * W2]);
    float s = Sin[((size_t)b * NC + c) * INNER + i];

    for (int k = 0; k < CL; k += 4) {
        float xn[4], bb[4];
#pragma unroll
        for (int j = 0; j < 4; j++) {
            int kk = k0 + k + 2 + j;
            xn[j] = (kk < KK) ? __half2float(col[(size_t)kk * W2]) : 0.f;
        }
#pragma unroll
        for (int j = 0; j < 4; j++)
            bb[j] = __half2float(bp[(size_t)(k0 + k + j) * W2]);
#pragma unroll
        for (int j = 0; j < 4; j++) {
            float x2 = xn[j];
            float cc = fmaf(w0, xm2, fmaf(w1, xm1, fmaf(w2, x0, fmaf(w3, x1, fmaf(w4, x2, cb)))));
            float u = cc / (1.0f + __expf(-cc));
            s = fmaf(asig, s, bt * u);
            float y = fmaf(gm, s, dl * u);
            gp[(size_t)(k0 + k + j) * INNER] = __float2half_rn(y * bb[j]);
            xm2 = xm1; xm1 = x0; x0 = x1; x1 = x2;
        }
    }
}

// ---------------- launch ----------------
extern "C" void kernel_launch(void* const* d_in, const int* in_sizes, int n_in,
                              void* d_out, int out_size)
{
    const float* x      = (const float*)d_in[0];
    const float* norm_w = (const float*)d_in[1];
    const float* Wa     = (const float*)d_in[2];
    const float* Wb     = (const float*)d_in[3];
    const float* conv_w = (const float*)d_in[4];
    const float* conv_b = (const float*)d_in[5];
    const float* alpha  = (const float*)d_in[6];
    const float* beta   = (const float*)d_in[7];
    const float* gamma  = (const float*)d_in[8];
    const float* delta  = (const float*)d_in[9];
    const float* Wout   = (const float*)d_in[10];
    float* out = (float*)d_out;

    float *st, *sin;
    __half *ab, *h16, *g16, *w2, *wo16;
    cudaGetSymbolAddress((void**)&ab,   g_ab);
    cudaGetSymbolAddress((void**)&st,   g_state);
    cudaGetSymbolAddress((void**)&sin,  g_sin);
    cudaGetSymbolAddress((void**)&h16,  g_h16);
    cudaGetSymbolAddress((void**)&g16,  g_g16);
    cudaGetSymbolAddress((void**)&w2,   g_w2);
    cudaGetSymbolAddress((void**)&wo16, g_wo16);

    cudaFuncSetAttribute(gemm_f16<true>,
                         cudaFuncAttributeMaxDynamicSharedMemorySize, GEMM_SMEM_BYTES);
    cudaFuncSetAttribute(gemm_f16<false>,
                         cudaFuncAttributeMaxDynamicSharedMemorySize, GEMM_SMEM_BYTES);

    // 1) rmsnorm -> fp16
    rmsnorm_kernel<<<MM / 8, 256>>>(x, norm_w, h16);

    // 2) weight conversions (fp16): [Wa;Wb] combined + Wout
    cvt_kernel<<<(INNER * DD / 4 + 255) / 256, 256>>>(Wa, w2, INNER * DD / 4);
    cvt_kernel<<<(INNER * DD / 4 + 255) / 256, 256>>>(Wb, w2 + (size_t)INNER * DD, INNER * DD / 4);
    cvt_kernel<<<(DD * INNER / 4 + 255) / 256, 256>>>(Wout, wo16, DD * INNER / 4);

    // 3) [a|b] = h @ [Wa;Wb]^T   (M=32768, N=2048, K=512), fp16 out
    {
        dim3 grid(W2 / 128, MM / 128);
        gemm_f16<true><<<grid, 256, GEMM_SMEM_BYTES>>>(h16, w2, ab, nullptr, W2, DD);
    }

    // 4) chunked parallel scan (3 passes)
    scan_state_kernel<<<BB * NC * INNER / 256, 256>>>(ab, conv_w, conv_b, alpha, beta, st);
    scan_prefix_kernel<<<BB * INNER / 256, 256>>>(st, alpha, sin);
    scan_apply_kernel<<<BB * NC * INNER / 256, 256>>>(
        ab, sin, g16, conv_w, conv_b, alpha, beta, gamma, delta);

    // 5) out = x + g @ Wout^T   (M=32768, N=512, K=1024), fp32 out + residual
    {
        dim3 grid(DD / 128, MM / 128);
        gemm_f16<false><<<grid, 256, GEMM_SMEM_BYTES>>>(g16, wo16, out, x, DD, INNER);
    }
}

// round 9
// speedup vs baseline: 7.8341x; 1.0762x over previous
#include <cuda_runtime.h>
#include <cuda_fp16.h>
#include <cstdint>

// ---------------- problem constants ----------------
#define BB    16
#define KK    2048
#define DD    512
#define INNER 1024
#define W2    (2*INNER)    // combined a|b row stride (halves)
#define KW    5
#define MM    (BB*KK)      // 32768
#define EPSV  1e-5f
#define NC    16           // scan chunks
#define CL    (KK/NC)      // 128
#define IH    (INNER/2)    // 512 half2 per inner row

// ---------------- scratch (device globals) ----------------
__device__ __half  g_ab [(size_t)MM * W2];     // [M, 2048]: a | b (fp16) 128MB
__device__ __half  g_u  [(size_t)MM * INNER];  // conv+silu out (fp16)  64MB
__device__ __half  g_h16[(size_t)MM * DD];     // rmsnorm out (fp16)
__device__ __half  g_g16[(size_t)MM * INNER];  // scan out    (fp16)
__device__ __half  g_w2 [W2 * DD];             // [Wa;Wb] fp16
__device__ __half  g_wo16[DD * INNER];
__device__ float   g_state[BB * NC * INNER];   // chunk-local final states

__device__ __forceinline__ uint32_t smem_u32(const void* p) {
    uint32_t a;
    asm("{ .reg .u64 t; cvta.to.shared.u64 t, %1; cvt.u32.u64 %0, t; }"
        : "=r"(a) : "l"(p));
    return a;
}

// ---------------- rmsnorm -> fp16 ----------------
__global__ __launch_bounds__(256) void rmsnorm_kernel(
    const float* __restrict__ x, const float* __restrict__ w,
    __half* __restrict__ h16)
{
    int row  = blockIdx.x * 8 + (threadIdx.x >> 5);
    int lane = threadIdx.x & 31;
    const float4* xp = reinterpret_cast<const float4*>(x + (size_t)row * DD);
    const float4* wp = reinterpret_cast<const float4*>(w);

    float4 v[4];
    float ss = 0.f;
#pragma unroll
    for (int j = 0; j < 4; j++) {
        v[j] = xp[lane + 32 * j];
        ss += v[j].x * v[j].x + v[j].y * v[j].y + v[j].z * v[j].z + v[j].w * v[j].w;
    }
#pragma unroll
    for (int off = 16; off > 0; off >>= 1)
        ss += __shfl_xor_sync(0xffffffffu, ss, off);

    float r = rsqrtf(ss * (1.0f / DD) + EPSV);

    __half* hb = h16 + (size_t)row * DD;
#pragma unroll
    for (int j = 0; j < 4; j++) {
        float4 wv = wp[lane + 32 * j];
        int col = (lane + 32 * j) * 4;
        __half2* hp = reinterpret_cast<__half2*>(hb + col);
        hp[0] = __floats2half2_rn(v[j].x * r * wv.x, v[j].y * r * wv.y);
        hp[1] = __floats2half2_rn(v[j].z * r * wv.z, v[j].w * r * wv.w);
    }
}

// ---------------- fp32 -> fp16 cast (weights), vectorized ----------------
__global__ __launch_bounds__(256) void cvt_kernel(
    const float* __restrict__ src, __half* __restrict__ dst, int n4)
{
    int i = blockIdx.x * 256 + threadIdx.x;
    if (i < n4) {
        float4 v = reinterpret_cast<const float4*>(src)[i];
        __half2* d = reinterpret_cast<__half2*>(dst) + i * 2;
        d[0] = __floats2half2_rn(v.x, v.y);
        d[1] = __floats2half2_rn(v.z, v.w);
    }
}

// ---------------- HMMA fp16 GEMM with ldmatrix, 3-stage pipeline ------------
#define RS 40
#define TILE_H (128 * RS)
#define TB (TILE_H * 2)
#define STAGE_B (2 * TB)
#define NSTAGE 3
#define GEMM_SMEM_BYTES (NSTAGE * STAGE_B)   // 61440

#define MMA_F16(c, a, b)                                                \
    asm volatile(                                                       \
        "mma.sync.aligned.m16n8k16.row.col.f32.f16.f16.f32 "            \
        "{%0,%1,%2,%3}, {%4,%5,%6,%7}, {%8,%9}, {%0,%1,%2,%3};"         \
        : "+f"((c)[0]), "+f"((c)[1]), "+f"((c)[2]), "+f"((c)[3])        \
        : "r"((a)[0]), "r"((a)[1]), "r"((a)[2]), "r"((a)[3]),           \
          "r"((b)[0]), "r"((b)[1]))

#define LDSM4(r0, r1, r2, r3, addr)                                     \
    asm volatile("ldmatrix.sync.aligned.m8n8.x4.shared.b16 "            \
                 "{%0,%1,%2,%3}, [%4];"                                 \
                 : "=r"(r0), "=r"(r1), "=r"(r2), "=r"(r3) : "r"(addr))

template <bool HALF_OUT>
__global__ __launch_bounds__(256, 2) void gemm_f16(
    const __half* __restrict__ A, const __half* __restrict__ B,
    void* __restrict__ Cv, const float* __restrict__ res, int N, int K)
{
    extern __shared__ uint16_t sm[];

    const int tid  = threadIdx.x;
    const int lane = tid & 31;
    const int wid  = tid >> 5;
    const int wm   = wid >> 2;
    const int wn   = wid & 3;
    const int r    = lane >> 2;
    const int cp   = (lane & 3) * 2;

    const size_t mBase = (size_t)blockIdx.y * 128;
    const size_t nBase = (size_t)blockIdx.x * 128;

    const __half* srcA = A + mBase * K;
    const __half* srcB = B + nBase * K;

    const uint32_t smem_base = smem_u32(sm);

    const uint32_t aLaneOff =
        (uint32_t)(((wm * 64 + ((lane >> 3) & 1) * 8 + (lane & 7)) * RS
                    + (lane >> 4) * 8) * 2);
    const uint32_t bLaneOff =
        (uint32_t)(((wn * 32 + ((lane >> 4) & 1) * 8 + (lane & 7)) * RS
                    + ((lane >> 3) & 1) * 8) * 2);

    const int lrow0 = tid >> 2;
    const int lseg  = tid & 3;
    auto load_stage = [&](int s, int kt) {
        uint32_t sb = smem_base + (uint32_t)s * STAGE_B;
#pragma unroll
        for (int rep = 0; rep < 2; rep++) {
            int row = lrow0 + rep * 64;
            uint32_t off = row * (RS * 2) + lseg * 16;
            size_t go = (size_t)row * K + kt * 32 + lseg * 8;
            asm volatile("cp.async.cg.shared.global [%0], [%1], 16;"
                         :: "r"(sb + off), "l"(srcA + go));
            asm volatile("cp.async.cg.shared.global [%0], [%1], 16;"
                         :: "r"(sb + TB + off), "l"(srcB + go));
        }
        asm volatile("cp.async.commit_group;" ::: "memory");
    };

    float acc[4][4][4];
#pragma unroll
    for (int i = 0; i < 4; i++)
#pragma unroll
        for (int j = 0; j < 4; j++)
#pragma unroll
            for (int q = 0; q < 4; q++) acc[i][j][q] = 0.f;

    const int nkt = K >> 5;

    load_stage(0, 0);
    load_stage(1, 1);

    int sc = 0;
    for (int kt = 0; kt < nkt; kt++) {
        if (kt + 1 < nkt) {
            asm volatile("cp.async.wait_group 1;" ::: "memory");
        } else {
            asm volatile("cp.async.wait_group 0;" ::: "memory");
        }
        __syncthreads();

        if (kt + 2 < nkt) {
            int s2 = sc + 2; if (s2 >= NSTAGE) s2 -= NSTAGE;
            load_stage(s2, kt + 2);
        }

        uint32_t sb = smem_base + (uint32_t)sc * STAGE_B;

#pragma unroll
        for (int k16 = 0; k16 < 32; k16 += 16) {
            uint32_t bh[4][2];
#pragma unroll
            for (int j = 0; j < 2; j++) {
                uint32_t ad = sb + TB + bLaneOff
                            + (uint32_t)((j * 16 * RS + k16) * 2);
                LDSM4(bh[2*j][0], bh[2*j][1], bh[2*j+1][0], bh[2*j+1][1], ad);
            }
#pragma unroll
            for (int mi = 0; mi < 4; mi++) {
                uint32_t a4[4];
                uint32_t ad = sb + aLaneOff + (uint32_t)((mi * 16 * RS + k16) * 2);
                LDSM4(a4[0], a4[1], a4[2], a4[3], ad);
#pragma unroll
                for (int ni = 0; ni < 4; ni++)
                    MMA_F16(acc[mi][ni], a4, bh[ni]);
            }
        }
        __syncthreads();
        if (++sc == NSTAGE) sc = 0;
    }

#pragma unroll
    for (int mi = 0; mi < 4; mi++) {
        size_t row0 = mBase + wm * 64 + mi * 16 + r;
#pragma unroll
        for (int ni = 0; ni < 4; ni++) {
            size_t col = nBase + wn * 32 + ni * 8 + cp;
            if (HALF_OUT) {
                __half* C = (__half*)Cv;
                *reinterpret_cast<__half2*>(C + row0 * N + col) =
                    __floats2half2_rn(acc[mi][ni][0], acc[mi][ni][1]);
                *reinterpret_cast<__half2*>(C + (row0 + 8) * N + col) =
                    __floats2half2_rn(acc[mi][ni][2], acc[mi][ni][3]);
            } else {
                float* C = (float*)Cv;
                float2 v0 = make_float2(acc[mi][ni][0], acc[mi][ni][1]);
                float2 v1 = make_float2(acc[mi][ni][2], acc[mi][ni][3]);
                if (res) {
                    float2 r0 = *reinterpret_cast<const float2*>(res + row0 * N + col);
                    float2 r1 = *reinterpret_cast<const float2*>(res + (row0 + 8) * N + col);
                    v0.x += r0.x; v0.y += r0.y;
                    v1.x += r1.x; v1.y += r1.y;
                }
                *reinterpret_cast<float2*>(C + row0 * N + col) = v0;
                *reinterpret_cast<float2*>(C + (row0 + 8) * N + col) = v1;
            }
        }
    }
}

// ---------------- scan pass 1: conv+silu -> u (fp16) + chunk states ---------
// Each thread: one channel PAIR (half2) over one K-chunk of 128.
__global__ __launch_bounds__(256) void scan_u_state_kernel(
    const __half2* __restrict__ ab2,     // [M, 1024] half2 rows (a|b)
    __half2* __restrict__ u2,            // [M, 512] half2
    const float* __restrict__ conv_w, const float* __restrict__ conv_b,
    const float* __restrict__ alpha, const float* __restrict__ beta,
    float2* __restrict__ S2)             // [B, NC, 512] float2
{
    int idx = blockIdx.x * 256 + threadIdx.x;  // 0 .. BB*NC*IH-1
    int i2 = idx & (IH - 1);
    int c  = (idx >> 9) & (NC - 1);
    int b  = idx >> 13;
    int i0 = i2 * 2;

    float2 w0 = make_float2(conv_w[i0*KW+0], conv_w[i0*KW+KW+0]);
    float2 w1 = make_float2(conv_w[i0*KW+1], conv_w[i0*KW+KW+1]);
    float2 w2 = make_float2(conv_w[i0*KW+2], conv_w[i0*KW+KW+2]);
    float2 w3 = make_float2(conv_w[i0*KW+3], conv_w[i0*KW+KW+3]);
    float2 w4 = make_float2(conv_w[i0*KW+4], conv_w[i0*KW+KW+4]);
    float2 cb = make_float2(conv_b[i0], conv_b[i0+1]);
    float2 as = make_float2(1.0f/(1.0f+__expf(-alpha[i0])),
                            1.0f/(1.0f+__expf(-alpha[i0+1])));
    float2 bt = make_float2(beta[i0], beta[i0+1]);

    const __half2* col = ab2 + (size_t)b * KK * (W2/2) + i2;
    __half2* up = u2 + (size_t)b * KK * IH + i2;
    int k0 = c * CL;

    float2 xm2 = (c > 0) ? __half22float2(col[(size_t)(k0-2) * (W2/2)]) : make_float2(0.f,0.f);
    float2 xm1 = (c > 0) ? __half22float2(col[(size_t)(k0-1) * (W2/2)]) : make_float2(0.f,0.f);
    float2 x0 = __half22float2(col[(size_t)k0 * (W2/2)]);
    float2 x1 = __half22float2(col[(size_t)(k0+1) * (W2/2)]);
    float2 s = make_float2(0.f, 0.f);

    for (int k = 0; k < CL; k += 8) {
        float2 xn[8];
#pragma unroll
        for (int j = 0; j < 8; j++) {
            int kk = k0 + k + 2 + j;
            xn[j] = (kk < KK) ? __half22float2(col[(size_t)kk * (W2/2)])
                              : make_float2(0.f, 0.f);
        }
#pragma unroll
        for (int j = 0; j < 8; j++) {
            float2 x2 = xn[j];
            float cx = fmaf(w0.x, xm2.x, fmaf(w1.x, xm1.x, fmaf(w2.x, x0.x,
                       fmaf(w3.x, x1.x, fmaf(w4.x, x2.x, cb.x)))));
            float cy = fmaf(w0.y, xm2.y, fmaf(w1.y, xm1.y, fmaf(w2.y, x0.y,
                       fmaf(w3.y, x1.y, fmaf(w4.y, x2.y, cb.y)))));
            float ux = __fdividef(cx, 1.0f + __expf(-cx));
            float uy = __fdividef(cy, 1.0f + __expf(-cy));
            s.x = fmaf(as.x, s.x, bt.x * ux);
            s.y = fmaf(as.y, s.y, bt.y * uy);
            up[(size_t)(k0 + k + j) * IH] = __floats2half2_rn(ux, uy);
            xm2 = xm1; xm1 = x0; x0 = x1; x1 = x2;
        }
    }
    S2[((size_t)b * NC + c) * IH + i2] = s;
}

// ---------------- scan pass 2: apply (prefix inlined) + gate -> g16 ---------
__global__ __launch_bounds__(256) void scan_apply_kernel(
    const __half2* __restrict__ ab2,     // b gate at half2 offset +IH
    const __half2* __restrict__ u2,
    const float2* __restrict__ S2,
    __half2* __restrict__ g2,
    const float* __restrict__ alpha, const float* __restrict__ beta,
    const float* __restrict__ gamma, const float* __restrict__ delta)
{
    int idx = blockIdx.x * 256 + threadIdx.x;
    int i2 = idx & (IH - 1);
    int c  = (idx >> 9) & (NC - 1);
    int b  = idx >> 13;
    int i0 = i2 * 2;

    float2 as = make_float2(1.0f/(1.0f+__expf(-alpha[i0])),
                            1.0f/(1.0f+__expf(-alpha[i0+1])));
    float2 bt = make_float2(beta[i0],  beta[i0+1]);
    float2 gm = make_float2(gamma[i0], gamma[i0+1]);
    float2 dl = make_float2(delta[i0], delta[i0+1]);

    // prefix: fold chunk states 0..c-1 with decay as^CL
    float2 aL = as;
#pragma unroll
    for (int q = 0; q < 7; q++) { aL.x *= aL.x; aL.y *= aL.y; }   // as^128

    float2 s = make_float2(0.f, 0.f);
    const float2* Sb = S2 + (size_t)b * NC * IH + i2;
    for (int cc = 0; cc < c; cc++) {
        float2 sv = Sb[(size_t)cc * IH];
        s.x = fmaf(aL.x, s.x, sv.x);
        s.y = fmaf(aL.y, s.y, sv.y);
    }

    const __half2* bp = ab2 + (size_t)b * KK * (W2/2) + IH + i2;
    const __half2* up = u2 + (size_t)b * KK * IH + i2;
    __half2* gp = g2 + (size_t)b * KK * IH + i2;
    int k0 = c * CL;

    for (int k = 0; k < CL; k += 8) {
        float2 uu[8], bb[8];
#pragma unroll
        for (int j = 0; j < 8; j++)
            uu[j] = __half22float2(up[(size_t)(k0 + k + j) * IH]);
#pragma unroll
        for (int j = 0; j < 8; j++)
            bb[j] = __half22float2(bp[(size_t)(k0 + k + j) * (W2/2)]);
#pragma unroll
        for (int j = 0; j < 8; j++) {
            s.x = fmaf(as.x, s.x, bt.x * uu[j].x);
            s.y = fmaf(as.y, s.y, bt.y * uu[j].y);
            float yx = fmaf(gm.x, s.x, dl.x * uu[j].x);
            float yy = fmaf(gm.y, s.y, dl.y * uu[j].y);
            gp[(size_t)(k0 + k + j) * IH] =
                __floats2half2_rn(yx * bb[j].x, yy * bb[j].y);
        }
    }
}

// ---------------- launch ----------------
extern "C" void kernel_launch(void* const* d_in, const int* in_sizes, int n_in,
                              void* d_out, int out_size)
{
    const float* x      = (const float*)d_in[0];
    const float* norm_w = (const float*)d_in[1];
    const float* Wa     = (const float*)d_in[2];
    const float* Wb     = (const float*)d_in[3];
    const float* conv_w = (const float*)d_in[4];
    const float* conv_b = (const float*)d_in[5];
    const float* alpha  = (const float*)d_in[6];
    const float* beta   = (const float*)d_in[7];
    const float* gamma  = (const float*)d_in[8];
    const float* delta  = (const float*)d_in[9];
    const float* Wout   = (const float*)d_in[10];
    float* out = (float*)d_out;

    float *st;
    __half *ab, *u, *h16, *g16, *w2, *wo16;
    cudaGetSymbolAddress((void**)&ab,   g_ab);
    cudaGetSymbolAddress((void**)&u,    g_u);
    cudaGetSymbolAddress((void**)&st,   g_state);
    cudaGetSymbolAddress((void**)&h16,  g_h16);
    cudaGetSymbolAddress((void**)&g16,  g_g16);
    cudaGetSymbolAddress((void**)&w2,   g_w2);
    cudaGetSymbolAddress((void**)&wo16, g_wo16);

    cudaFuncSetAttribute(gemm_f16<true>,
                         cudaFuncAttributeMaxDynamicSharedMemorySize, GEMM_SMEM_BYTES);
    cudaFuncSetAttribute(gemm_f16<false>,
                         cudaFuncAttributeMaxDynamicSharedMemorySize, GEMM_SMEM_BYTES);

    // 1) rmsnorm -> fp16
    rmsnorm_kernel<<<MM / 8, 256>>>(x, norm_w, h16);

    // 2) weight conversions (fp16): [Wa;Wb] combined + Wout
    cvt_kernel<<<(INNER * DD / 4 + 255) / 256, 256>>>(Wa, w2, INNER * DD / 4);
    cvt_kernel<<<(INNER * DD / 4 + 255) / 256, 256>>>(Wb, w2 + (size_t)INNER * DD, INNER * DD / 4);
    cvt_kernel<<<(DD * INNER / 4 + 255) / 256, 256>>>(Wout, wo16, DD * INNER / 4);

    // 3) [a|b] = h @ [Wa;Wb]^T   (M=32768, N=2048, K=512), fp16 out
    {
        dim3 grid(W2 / 128, MM / 128);
        gemm_f16<true><<<grid, 256, GEMM_SMEM_BYTES>>>(h16, w2, ab, nullptr, W2, DD);
    }

    // 4) scan: pass1 (u + chunk states), pass2 (prefix-inlined apply)
    {
        int nthr = BB * NC * IH;          // 131072
        scan_u_state_kernel<<<nthr / 256, 256>>>(
            (const __half2*)ab, (__half2*)u, conv_w, conv_b, alpha, beta,
            (float2*)st);
        scan_apply_kernel<<<nthr / 256, 256>>>(
            (const __half2*)ab, (const __half2*)u, (const float2*)st,
            (__half2*)g16, alpha, beta, gamma, delta);
    }

    // 5) out = x + g @ Wout^T   (M=32768, N=512, K=1024), fp32 out + residual
    {
        dim3 grid(DD / 128, MM / 128);
        gemm_f16<false><<<grid, 256, GEMM_SMEM_BYTES>>>(g16, wo16, out, x, DD, INNER);
    }
}